// round 10
// baseline (speedup 1.0000x reference)
#include <cuda_runtime.h>
#include <cuda_bf16.h>
#include <cstdint>

#define MAX_NODES 100000
#define MAX_EDGES 1600000
#define INF  256
#define HIDF 128
#define OUTF 64
#define SCAN_BS 1024

// ---------------- device scratch ----------------------------------------------
__device__ __align__(128) __nv_bfloat16 g_h  [(size_t)MAX_NODES * HIDF];
__device__ __align__(128) __nv_bfloat16 g_g  [(size_t)MAX_NODES * OUTF];
__device__ __align__(128) float g_dinv[MAX_NODES];
__device__ __align__(128) int   g_cnt   [MAX_NODES];
__device__ __align__(128) int   g_rowptr[MAX_NODES + 1];
__device__ __align__(128) int   g_cursor[MAX_NODES];
__device__ __align__(128) int   g_adj   [MAX_EDGES];
__device__ __align__(128) int   g_bsum  [256];
__device__ __align__(128) int   g_boff  [256];
__device__ __align__(128) float g_w1t [INF * HIDF];
__device__ __align__(128) __nv_bfloat16 g_w2hi[HIDF * OUTF];
__device__ __align__(128) __nv_bfloat16 g_w2lo[HIDF * OUTF];

// ================= helpers ======================================================
__device__ __forceinline__ uint32_t smem_u32(const void* p) {
    uint32_t a;
    asm("{ .reg .u64 t; cvta.to.shared.u64 t, %1; cvt.u32.u64 %0, t; }" : "=r"(a) : "l"(p));
    return a;
}
__device__ __forceinline__ void ldsm_x4(uint32_t* r, uint32_t addr) {
    asm volatile("ldmatrix.sync.aligned.m8n8.x4.shared.b16 {%0,%1,%2,%3}, [%4];"
                 : "=r"(r[0]), "=r"(r[1]), "=r"(r[2]), "=r"(r[3]) : "r"(addr));
}
__device__ __forceinline__ void ldsm_x2(uint32_t* r, uint32_t addr) {
    asm volatile("ldmatrix.sync.aligned.m8n8.x2.shared.b16 {%0,%1}, [%2];"
                 : "=r"(r[0]), "=r"(r[1]) : "r"(addr));
}
__device__ __forceinline__ void mma_bf16(float* d, const uint32_t* a, const uint32_t* b) {
    asm volatile(
        "mma.sync.aligned.m16n8k16.row.col.f32.bf16.bf16.f32 "
        "{%0,%1,%2,%3}, {%4,%5,%6,%7}, {%8,%9}, {%0,%1,%2,%3};"
        : "+f"(d[0]), "+f"(d[1]), "+f"(d[2]), "+f"(d[3])
        : "r"(a[0]), "r"(a[1]), "r"(a[2]), "r"(a[3]), "r"(b[0]), "r"(b[1]));
}
__device__ __forceinline__ void mma_tf32(float* d, const uint32_t* a, const uint32_t* b) {
    asm volatile(
        "mma.sync.aligned.m16n8k8.row.col.f32.tf32.tf32.f32 "
        "{%0,%1,%2,%3}, {%4,%5,%6,%7}, {%8,%9}, {%0,%1,%2,%3};"
        : "+f"(d[0]), "+f"(d[1]), "+f"(d[2]), "+f"(d[3])
        : "r"(a[0]), "r"(a[1]), "r"(a[2]), "r"(a[3]), "r"(b[0]), "r"(b[1]));
}
__device__ __forceinline__ void cp16(uint32_t dst, const void* src, bool valid) {
    int sz = valid ? 16 : 0;
    asm volatile("cp.async.cg.shared.global [%0], [%1], 16, %2;"
                 :: "r"(dst), "l"(src), "r"(sz) : "memory");
}
#define CP_COMMIT() asm volatile("cp.async.commit_group;" ::: "memory")
#define CP_WAIT(n)  asm volatile("cp.async.wait_group %0;" :: "n"(n) : "memory")

// exact bf16x2 -> 2x f32 via bit ops (ALU pipe, no CVT)
__device__ __forceinline__ void bq8(const uint4& q, float* f) {
    f[0] = __uint_as_float(q.x << 16); f[1] = __uint_as_float(q.x & 0xffff0000u);
    f[2] = __uint_as_float(q.y << 16); f[3] = __uint_as_float(q.y & 0xffff0000u);
    f[4] = __uint_as_float(q.z << 16); f[5] = __uint_as_float(q.z & 0xffff0000u);
    f[6] = __uint_as_float(q.w << 16); f[7] = __uint_as_float(q.w & 0xffff0000u);
}
__device__ __forceinline__ void acc8(float* acc, const uint4& q, float nrm) {
    float f[8]; bq8(q, f);
    #pragma unroll
    for (int i = 0; i < 8; i++) acc[i] = fmaf(nrm, f[i], acc[i]);
}

// ================= CSR build ====================================================
__global__ void count_kernel(const int* __restrict__ dst, int E, int* __restrict__ cnt) {
    int i = blockIdx.x * blockDim.x + threadIdx.x;
    if (i < E) atomicAdd(&cnt[dst[i]], 1);
}
__global__ void scanA_kernel(const int* __restrict__ cnt, int n, int* __restrict__ bsum) {
    int i = blockIdx.x * SCAN_BS + threadIdx.x;
    int c = (i < n) ? cnt[i] : 0;
    int lane = threadIdx.x & 31, wid = threadIdx.x >> 5;
    #pragma unroll
    for (int o = 16; o > 0; o >>= 1) c += __shfl_xor_sync(~0u, c, o);
    __shared__ int ws[32];
    if (lane == 0) ws[wid] = c;
    __syncthreads();
    if (threadIdx.x < 32) {
        int v = ws[threadIdx.x];
        #pragma unroll
        for (int o = 16; o > 0; o >>= 1) v += __shfl_xor_sync(~0u, v, o);
        if (threadIdx.x == 0) bsum[blockIdx.x] = v;
    }
}
__global__ void scanB_kernel(const int* __restrict__ bsum, int nb,
                             int* __restrict__ boff, int* __restrict__ rowptr,
                             int n, int E) {
    int t = threadIdx.x;
    int v = (t < nb) ? bsum[t] : 0;
    int lane = t & 31, w = t >> 5;
    int incl = v;
    #pragma unroll
    for (int o = 1; o < 32; o <<= 1) {
        int u = __shfl_up_sync(~0u, incl, o);
        if (lane >= o) incl += u;
    }
    __shared__ int ws[4];
    if (lane == 31) ws[w] = incl;
    __syncthreads();
    int add = 0;
    #pragma unroll
    for (int k = 0; k < 4; k++) if (k < w) add += ws[k];
    if (t < nb) boff[t] = incl - v + add;
    if (t == 0) rowptr[n] = E;
}
__global__ void scanC_kernel(const int* __restrict__ cnt, const int* __restrict__ boff,
                             int n, int* __restrict__ rowptr, int* __restrict__ cursor,
                             float* __restrict__ dinv) {
    int i = blockIdx.x * SCAN_BS + threadIdx.x;
    int c = (i < n) ? cnt[i] : 0;
    int lane = threadIdx.x & 31, wid = threadIdx.x >> 5;
    int v = c;
    #pragma unroll
    for (int o = 1; o < 32; o <<= 1) {
        int t = __shfl_up_sync(~0u, v, o);
        if (lane >= o) v += t;
    }
    __shared__ int ws[32];
    if (lane == 31) ws[wid] = v;
    __syncthreads();
    if (threadIdx.x < 32) {
        int w = ws[threadIdx.x];
        #pragma unroll
        for (int o = 1; o < 32; o <<= 1) {
            int t = __shfl_up_sync(~0u, w, o);
            if ((int)threadIdx.x >= o) w += t;
        }
        ws[threadIdx.x] = w;
    }
    __syncthreads();
    int excl = v - c + (wid > 0 ? ws[wid - 1] : 0) + boff[blockIdx.x];
    if (i < n) {
        rowptr[i] = excl;
        cursor[i] = excl;
        dinv[i] = rsqrtf((float)c + 1.0f);
    }
}
__global__ void fill_kernel(const int* __restrict__ src, const int* __restrict__ dst,
                            int E, int* __restrict__ cursor, int* __restrict__ adj) {
    int i = blockIdx.x * blockDim.x + threadIdx.x;
    if (i < E) {
        int pos = atomicAdd(&cursor[dst[i]], 1);
        adj[pos] = src[i];
    }
}

// ================= weight prep ==================================================
__global__ void wtf32_kernel(const float* __restrict__ W, int K, int N,
                             float* __restrict__ img) {
    int idx = blockIdx.x * blockDim.x + threadIdx.x;
    if (idx >= K * N) return;
    int k = idx / N, n = idx % N;
    int c = k >> 6, kk = k & 63;
    uint32_t off = (uint32_t)(n * 256 + kk * 4);
    uint32_t sw = off ^ (((off >> 8) & 7) << 4);
    img[((size_t)c * N * 256 + sw) / 4] = W[(size_t)k * N + n];
}
__global__ void wsplit_kernel(const float* __restrict__ W, int K, int N,
                              __nv_bfloat16* __restrict__ hi, __nv_bfloat16* __restrict__ lo) {
    int idx = blockIdx.x * blockDim.x + threadIdx.x;
    if (idx >= K * N) return;
    int k = idx / N, n = idx % N;
    float w = W[(size_t)k * N + n];
    __nv_bfloat16 h = __float2bfloat16(w);
    __nv_bfloat16 l = __float2bfloat16(w - __bfloat162float(h));
    int c = k >> 6, kk = k & 63;
    uint32_t off = (uint32_t)(n * 128 + kk * 2);
    uint32_t sw = off ^ ((off >> 3) & 0x70);
    size_t pos = ((size_t)c * N * 128 + sw) / 2;
    hi[pos] = h;
    lo[pos] = l;
}

// ================= GEMM1: persistent tf32, 512 threads, cp.async ==============
__global__ __launch_bounds__(512, 1)
void tf32_gemm(const float* __restrict__ A, int lda, const float* __restrict__ img,
               __nv_bfloat16* __restrict__ C, int M, int ntiles)
{
    constexpr int NT  = HIDF;
    constexpr int KCH = 4;
    constexpr int BCH = NT * 256;
    constexpr int BB  = KCH * BCH;
    constexpr int OFF_A = BB;
    constexpr int ASTG = 32768;
    constexpr int NF  = 4;

    extern __shared__ char smraw[];
    char* sp = (char*)((((uintptr_t)smraw) + 1023) & ~(uintptr_t)1023);
    const uint32_t sb = smem_u32(sp);
    const uint32_t sbA = sb + OFF_A;

    const int tid = threadIdx.x;
    const int wid = tid >> 5;
    const int l   = tid & 31;
    const int warp_m = wid & 3;
    const int warp_n = wid >> 2;

    {
        const uint4* s = (const uint4*)img;
        uint4* d = (uint4*)sp;
        for (int i = tid; i < BB / 16; i += 512) d[i] = s[i];
    }

    const uint32_t xorm = (uint32_t)(l & 7) << 4;
    const uint32_t aRow = warp_m * 32 + (l & 15);
    const uint32_t aK16 = (uint32_t)(l >> 4);
    const uint32_t bN   = warp_n * 32 + (l & 7);
    const uint32_t bK16 = (uint32_t)((l >> 3) & 1);
    const int g  = l >> 2;
    const int t2 = (l & 3) * 2;

    for (int tile = blockIdx.x; tile < ntiles; tile += gridDim.x) {
        const int blockRow = tile * 128;

        float acc[2][NF][4];
        #pragma unroll
        for (int i = 0; i < 2; i++)
            #pragma unroll
            for (int j = 0; j < NF; j++)
                #pragma unroll
                for (int q = 0; q < 4; q++) acc[i][j][q] = 0.f;

        #pragma unroll
        for (int v = 0; v < 4; v++) {
            int vid = tid + v * 512;
            int row = vid >> 4;
            int u   = vid & 15;
            int grow = blockRow + row;
            bool valid = grow < M;
            const float* src = A + (size_t)(valid ? grow : 0) * lda + u * 4;
            uint32_t dst = sbA + row * 256 + (((uint32_t)u * 16) ^ (((uint32_t)row & 7) << 4));
            cp16(dst, src, valid);
        }
        CP_COMMIT();

        for (int c = 0; c < KCH; c++) {
            const int buf = c & 1;
            if (c + 1 < KCH) {
                const int nb = (c + 1) & 1;
                #pragma unroll
                for (int v = 0; v < 4; v++) {
                    int vid = tid + v * 512;
                    int row = vid >> 4;
                    int u   = vid & 15;
                    int grow = blockRow + row;
                    bool valid = grow < M;
                    const float* src = A + (size_t)(valid ? grow : 0) * lda + (c + 1) * 64 + u * 4;
                    uint32_t dst = sbA + nb * ASTG + row * 256
                                 + (((uint32_t)u * 16) ^ (((uint32_t)row & 7) << 4));
                    cp16(dst, src, valid);
                }
                CP_COMMIT();
                CP_WAIT(1);
            } else {
                CP_WAIT(0);
            }
            __syncthreads();

            const uint32_t aB = sbA + buf * ASTG;
            const uint32_t bB = sb + c * BCH;
            #pragma unroll
            for (int s = 0; s < 8; s++) {
                const uint32_t koff = (uint32_t)s * 32;
                uint32_t bf[NF][2];
                #pragma unroll
                for (int j = 0; j < NF; j++)
                    ldsm_x2(bf[j], bB + (bN + j * 8) * 256 + ((koff + bK16 * 16) ^ xorm));
                #pragma unroll
                for (int i = 0; i < 2; i++) {
                    uint32_t af[4];
                    ldsm_x4(af, aB + (aRow + i * 16) * 256 + ((koff + aK16 * 16) ^ xorm));
                    #pragma unroll
                    for (int j = 0; j < NF; j++)
                        mma_tf32(acc[i][j], af, bf[j]);
                }
            }
            __syncthreads();
        }

        #pragma unroll
        for (int i = 0; i < 2; i++) {
            int row0 = blockRow + warp_m * 32 + i * 16 + g;
            #pragma unroll
            for (int j = 0; j < NF; j++) {
                int col = warp_n * 32 + j * 8 + t2;
                if (row0 < M) {
                    __nv_bfloat162 v = __floats2bfloat162_rn(acc[i][j][0], acc[i][j][1]);
                    *(__nv_bfloat162*)(C + (size_t)row0 * NT + col) = v;
                }
                if (row0 + 8 < M) {
                    __nv_bfloat162 v = __floats2bfloat162_rn(acc[i][j][2], acc[i][j][3]);
                    *(__nv_bfloat162*)(C + (size_t)(row0 + 8) * NT + col) = v;
                }
            }
        }
    }
}

// ================= FUSED agg1 + GEMM2 ==========================================
// Per 128-node tile: gather-aggregate gcn1 (bias+relu+CRF mix) into a swizzled
// bf16 SMEM A-tile, then 2-term W2 MMA, write g. h2 never touches gmem.
__global__ __launch_bounds__(256, 2)
void agg1gemm2_kernel(const __nv_bfloat16* __restrict__ h, const int* __restrict__ rowptr,
                      const int* __restrict__ adj, const float* __restrict__ dinv,
                      const float* __restrict__ b1,
                      const __nv_bfloat16* __restrict__ imgHi,
                      const __nv_bfloat16* __restrict__ imgLo,
                      __nv_bfloat16* __restrict__ gout, int n, int ntiles)
{
    constexpr int NT  = OUTF;        // 64
    constexpr int BCH = NT * 128;    // 8KB per W2 chunk per array
    constexpr int BB  = 2 * BCH;     // 16KB per array
    constexpr int OFF_BLO = BB;
    constexpr int OFF_A   = 2 * BB;  // A tiles: 2 chunks x 16KB
    constexpr int ACH = 16384;
    constexpr int NF  = 2;           // 16 cols per warp

    extern __shared__ char smraw[];
    char* sp = (char*)((((uintptr_t)smraw) + 1023) & ~(uintptr_t)1023);
    const uint32_t sb = smem_u32(sp);

    const int tid = threadIdx.x;
    const int wid = tid >> 5;
    const int l   = tid & 31;

    // W2 images -> SMEM once
    {
        const uint4* shi = (const uint4*)imgHi;
        const uint4* slo = (const uint4*)imgLo;
        uint4* dhi = (uint4*)sp;
        uint4* dlo = (uint4*)(sp + OFF_BLO);
        for (int i = tid; i < BB / 16; i += 256) { dhi[i] = shi[i]; dlo[i] = slo[i]; }
    }

    // gather-phase constants
    const int sub = tid & 15;               // lane within node (16 lanes)
    const int rofs = tid >> 4;              // 0..15: row within pass
    const size_t fo = (size_t)sub * 8;      // feature offset (8 bf16)
    const int chunk = sub >> 3;             // which 64-K chunk
    const int uu = sub & 7;                 // 16B unit within chunk row

    // MMA-phase constants (as bf16_gemm)
    const uint32_t xorm = (uint32_t)(l & 7) << 4;
    const uint32_t aRow = (wid & 1) * 64 + (l & 15);
    const uint32_t aK8  = (uint32_t)(l >> 4) * 8;
    const uint32_t bN   = (wid >> 1) * 16 + (l & 7);
    const uint32_t bK8  = (uint32_t)((l >> 3) & 1) * 8;
    const int g  = l >> 2;
    const int t2 = (l & 3) * 2;

    // bias slice for this lane
    float4 bv0 = *(const float4*)(b1 + fo);
    float4 bv1 = *(const float4*)(b1 + fo + 4);
    float bb[8] = {bv0.x, bv0.y, bv0.z, bv0.w, bv1.x, bv1.y, bv1.z, bv1.w};

    __syncthreads();   // W2 copy visible

    for (int tile = blockIdx.x; tile < ntiles; tile += gridDim.x) {
        const int blockRow = tile * 128;

        // ---- phase 1: gather-aggregate 128 nodes, 16/pass ----
        #pragma unroll 1
        for (int p = 0; p < 8; p++) {
            int r = p * 16 + rofs;
            int node = blockRow + r;
            float acc[8];
            #pragma unroll
            for (int i = 0; i < 8; i++) acc[i] = 0.f;
            uint32_t o01 = 0, o23 = 0, o45 = 0, o67 = 0;
            if (node < n) {
                int beg = rowptr[node], end = rowptr[node + 1];
                float dd = dinv[node];
                int e = beg;
                for (; e + 4 <= end; e += 4) {
                    int s0 = __ldg(adj + e),     s1 = __ldg(adj + e + 1);
                    int s2 = __ldg(adj + e + 2), s3 = __ldg(adj + e + 3);
                    float n0 = __ldg(dinv + s0) * dd, n1 = __ldg(dinv + s1) * dd;
                    float n2 = __ldg(dinv + s2) * dd, n3 = __ldg(dinv + s3) * dd;
                    uint4 q0 = *(const uint4*)(h + (size_t)s0 * HIDF + fo);
                    uint4 q1 = *(const uint4*)(h + (size_t)s1 * HIDF + fo);
                    uint4 q2 = *(const uint4*)(h + (size_t)s2 * HIDF + fo);
                    uint4 q3 = *(const uint4*)(h + (size_t)s3 * HIDF + fo);
                    acc8(acc, q0, n0); acc8(acc, q1, n1);
                    acc8(acc, q2, n2); acc8(acc, q3, n3);
                }
                for (; e < end; e++) {
                    int s0 = __ldg(adj + e);
                    float n0 = __ldg(dinv + s0) * dd;
                    uint4 q0 = *(const uint4*)(h + (size_t)s0 * HIDF + fo);
                    acc8(acc, q0, n0);
                }
                float d2 = dd * dd;
                uint4 qs = *(const uint4*)(h + (size_t)node * HIDF + fo);
                float sf[8]; bq8(qs, sf);
                float r8[8];
                #pragma unroll
                for (int i = 0; i < 8; i++) {
                    float t = fmaf(d2, sf[i], acc[i]) + bb[i];
                    r8[i] = 0.9f * fmaxf(t, 0.f) + 0.1f;
                }
                __nv_bfloat162 p01 = __floats2bfloat162_rn(r8[0], r8[1]);
                __nv_bfloat162 p23 = __floats2bfloat162_rn(r8[2], r8[3]);
                __nv_bfloat162 p45 = __floats2bfloat162_rn(r8[4], r8[5]);
                __nv_bfloat162 p67 = __floats2bfloat162_rn(r8[6], r8[7]);
                o01 = *reinterpret_cast<uint32_t*>(&p01);
                o23 = *reinterpret_cast<uint32_t*>(&p23);
                o45 = *reinterpret_cast<uint32_t*>(&p45);
                o67 = *reinterpret_cast<uint32_t*>(&p67);
            }
            // store to swizzled A tile (same layout cp.async produced before)
            uint32_t dst = sb + OFF_A + chunk * ACH + r * 128
                         + (((uint32_t)uu * 16) ^ (((uint32_t)r & 7) << 4));
            *(uint4*)(sp + (dst - sb)) = make_uint4(o01, o23, o45, o67);
        }
        __syncthreads();

        // ---- phase 2: MMA g = h2 @ W2 (2-term) ----
        float acc[4][NF][4];
        #pragma unroll
        for (int i = 0; i < 4; i++)
            #pragma unroll
            for (int j = 0; j < NF; j++)
                #pragma unroll
                for (int q = 0; q < 4; q++) acc[i][j][q] = 0.f;

        #pragma unroll
        for (int c = 0; c < 2; c++) {
            const uint32_t aB = sb + OFF_A + c * ACH + aRow * 128;
            const uint32_t bHiBase = sb + c * BCH + bN * 128;
            const uint32_t bLoBase = bHiBase + OFF_BLO;
            #pragma unroll
            for (int s = 0; s < 4; s++) {
                const uint32_t akOff = ((uint32_t)(s * 16 + aK8) * 2) ^ xorm;
                const uint32_t bkOff = ((uint32_t)(s * 16 + bK8) * 2) ^ xorm;
                uint32_t bh[NF][2], bl[NF][2];
                #pragma unroll
                for (int j = 0; j < NF; j++) {
                    ldsm_x2(bh[j], bHiBase + j * 1024 + bkOff);
                    ldsm_x2(bl[j], bLoBase + j * 1024 + bkOff);
                }
                #pragma unroll
                for (int i = 0; i < 4; i++) {
                    uint32_t ah[4];
                    ldsm_x4(ah, aB + i * 2048 + akOff);
                    #pragma unroll
                    for (int j = 0; j < NF; j++) {
                        mma_bf16(acc[i][j], ah, bh[j]);
                        mma_bf16(acc[i][j], ah, bl[j]);
                    }
                }
            }
        }

        #pragma unroll
        for (int i = 0; i < 4; i++) {
            int row0 = blockRow + (wid & 1) * 64 + i * 16 + g;
            #pragma unroll
            for (int j = 0; j < NF; j++) {
                int col = (wid >> 1) * 16 + j * 8 + t2;
                if (row0 < n) {
                    __nv_bfloat162 v = __floats2bfloat162_rn(acc[i][j][0], acc[i][j][1]);
                    *(__nv_bfloat162*)(gout + (size_t)row0 * NT + col) = v;
                }
                if (row0 + 8 < n) {
                    __nv_bfloat162 v = __floats2bfloat162_rn(acc[i][j][2], acc[i][j][3]);
                    *(__nv_bfloat162*)(gout + (size_t)(row0 + 8) * NT + col) = v;
                }
            }
        }
        __syncthreads();  // protect A tile before next iteration overwrites
    }
}

// ================= agg2: 8 lanes/node, uint4 loads, 4-edge unroll ==============
__global__ void agg2_kernel(const __nv_bfloat16* __restrict__ g, const int* __restrict__ rowptr,
                            const int* __restrict__ adj, const float* __restrict__ dinv,
                            const float* __restrict__ b2, float* __restrict__ out, int n)
{
    int node = (blockIdx.x * blockDim.x + threadIdx.x) >> 3;
    int sub  = threadIdx.x & 7;
    if (node >= n) return;
    int beg = rowptr[node], end = rowptr[node + 1];
    float dd = dinv[node];
    const size_t fo = (size_t)sub * 8;

    float acc[8];
    #pragma unroll
    for (int i = 0; i < 8; i++) acc[i] = 0.f;

    int e = beg;
    for (; e + 4 <= end; e += 4) {
        int s0 = __ldg(adj + e),     s1 = __ldg(adj + e + 1);
        int s2 = __ldg(adj + e + 2), s3 = __ldg(adj + e + 3);
        float n0 = __ldg(dinv + s0) * dd, n1 = __ldg(dinv + s1) * dd;
        float n2 = __ldg(dinv + s2) * dd, n3 = __ldg(dinv + s3) * dd;
        uint4 q0 = *(const uint4*)(g + (size_t)s0 * OUTF + fo);
        uint4 q1 = *(const uint4*)(g + (size_t)s1 * OUTF + fo);
        uint4 q2 = *(const uint4*)(g + (size_t)s2 * OUTF + fo);
        uint4 q3 = *(const uint4*)(g + (size_t)s3 * OUTF + fo);
        acc8(acc, q0, n0); acc8(acc, q1, n1); acc8(acc, q2, n2); acc8(acc, q3, n3);
    }
    for (; e < end; e++) {
        int s0 = __ldg(adj + e);
        float n0 = __ldg(dinv + s0) * dd;
        uint4 q0 = *(const uint4*)(g + (size_t)s0 * OUTF + fo);
        acc8(acc, q0, n0);
    }

    float d2 = dd * dd;
    uint4 qs = *(const uint4*)(g + (size_t)node * OUTF + fo);
    float sf[8]; bq8(qs, sf);
    float4 bv0 = *(const float4*)(b2 + fo);
    float4 bv1 = *(const float4*)(b2 + fo + 4);
    float bb[8] = {bv0.x, bv0.y, bv0.z, bv0.w, bv1.x, bv1.y, bv1.z, bv1.w};
    float v[8];
    #pragma unroll
    for (int i = 0; i < 8; i++) v[i] = fmaf(d2, sf[i], acc[i]) + bb[i];

    float m = v[0];
    #pragma unroll
    for (int i = 1; i < 8; i++) m = fmaxf(m, v[i]);
    #pragma unroll
    for (int o = 4; o > 0; o >>= 1) m = fmaxf(m, __shfl_xor_sync(~0u, m, o, 8));
    float s = 0.f;
    #pragma unroll
    for (int i = 0; i < 8; i++) s += expf(v[i] - m);
    #pragma unroll
    for (int o = 4; o > 0; o >>= 1) s += __shfl_xor_sync(~0u, s, o, 8);
    float ls = m + logf(s);

    float* op = out + (size_t)node * OUTF + fo;
    *(float4*)(op)     = make_float4(v[0]-ls, v[1]-ls, v[2]-ls, v[3]-ls);
    *(float4*)(op + 4) = make_float4(v[4]-ls, v[5]-ls, v[6]-ls, v[7]-ls);
}

// ================= launch =======================================================
extern "C" void kernel_launch(void* const* d_in, const int* in_sizes, int n_in,
                              void* d_out, int out_size)
{
    const float* x  = (const float*)d_in[0];
    const int*   ei = (const int*)  d_in[1];
    // d_in[2] edge_weight: unused (CRF softmax over singleton groups == 1.0)
    const float* W1 = (const float*)d_in[3];
    const float* b1 = (const float*)d_in[4];
    const float* W2 = (const float*)d_in[5];
    const float* b2 = (const float*)d_in[6];
    float* out = (float*)d_out;

    const int n = in_sizes[0] / INF;
    const int E = in_sizes[2];
    const int* src = ei;
    const int* dst = ei + E;

    __nv_bfloat16 *h, *g, *w2hi, *w2lo;
    float *dinv, *w1t;
    int *cnt, *rowptr, *cursor, *adj, *bsum, *boff;
    cudaGetSymbolAddress((void**)&h,     g_h);
    cudaGetSymbolAddress((void**)&g,     g_g);
    cudaGetSymbolAddress((void**)&dinv,  g_dinv);
    cudaGetSymbolAddress((void**)&cnt,   g_cnt);
    cudaGetSymbolAddress((void**)&rowptr,g_rowptr);
    cudaGetSymbolAddress((void**)&cursor,g_cursor);
    cudaGetSymbolAddress((void**)&adj,   g_adj);
    cudaGetSymbolAddress((void**)&bsum,  g_bsum);
    cudaGetSymbolAddress((void**)&boff,  g_boff);
    cudaGetSymbolAddress((void**)&w1t,   g_w1t);
    cudaGetSymbolAddress((void**)&w2hi,  g_w2hi);
    cudaGetSymbolAddress((void**)&w2lo,  g_w2lo);

    const int nb = (n + SCAN_BS - 1) / SCAN_BS;
    const int mtiles = (n + 127) / 128;

    constexpr int SMEM1 = INF * HIDF * 4 + 2 * 32768 + 1024;
    constexpr int SMEMF = 2 * (HIDF * OUTF * 2) + 2 * 16384 + 1024;  // W2 32K + A 32K
    cudaFuncSetAttribute(tf32_gemm,        cudaFuncAttributeMaxDynamicSharedMemorySize, SMEM1);
    cudaFuncSetAttribute(agg1gemm2_kernel, cudaFuncAttributeMaxDynamicSharedMemorySize, SMEMF);

    static cudaStream_t sCsr = nullptr;
    static cudaEvent_t evFork = nullptr, evJoin = nullptr;
    if (!sCsr) {
        cudaStreamCreateWithFlags(&sCsr, cudaStreamNonBlocking);
        cudaEventCreateWithFlags(&evFork, cudaEventDisableTiming);
        cudaEventCreateWithFlags(&evJoin, cudaEventDisableTiming);
    }

    cudaEventRecord(evFork, 0);
    cudaStreamWaitEvent(sCsr, evFork, 0);

    // submission order keeps tf32_gemm at launch slot 5 for ncu (-s 5):
    cudaMemsetAsync(cnt, 0, (size_t)n * sizeof(int), sCsr);                     // 1
    count_kernel<<<(E + 255)/256, 256, 0, sCsr>>>(dst, E, cnt);                 // 2
    scanA_kernel<<<nb, SCAN_BS, 0, sCsr>>>(cnt, n, bsum);                       // 3
    wtf32_kernel<<<(INF*HIDF + 255)/256, 256>>>(W1, INF, HIDF, w1t);            // 4
    tf32_gemm<<<148, 512, SMEM1>>>(x, INF, w1t, h, n, mtiles);                  // 5
    scanB_kernel<<<1, 128, 0, sCsr>>>(bsum, nb, boff, rowptr, n, E);            // 6
    scanC_kernel<<<nb, SCAN_BS, 0, sCsr>>>(cnt, boff, n, rowptr, cursor, dinv); // 7
    fill_kernel <<<(E + 255)/256, 256, 0, sCsr>>>(src, dst, E, cursor, adj);    // 8
    wsplit_kernel<<<(HIDF*OUTF + 255)/256, 256, 0, sCsr>>>(W2, HIDF, OUTF, w2hi, w2lo);
    cudaEventRecord(evJoin, sCsr);
    cudaStreamWaitEvent(0, evJoin, 0);

    // fused agg1 + GEMM2 (persistent, 2 CTA/SM)
    agg1gemm2_kernel<<<296, 256, SMEMF>>>(h, rowptr, adj, dinv, b1,
                                          w2hi, w2lo, g, n, mtiles);

    agg2_kernel<<<((long long)n*8 + 255)/256, 256>>>(g, rowptr, adj, dinv, b2, out, n);
}

// round 11
// speedup vs baseline: 1.1494x; 1.1494x over previous
#include <cuda_runtime.h>
#include <cuda_bf16.h>
#include <cstdint>

#define MAX_NODES 100000
#define MAX_EDGES 1600000
#define INF  256
#define HIDF 128
#define OUTF 64
#define SCAN_BS 1024

// ---------------- device scratch ----------------------------------------------
__device__ __align__(128) __nv_bfloat16 g_h  [(size_t)MAX_NODES * HIDF];
__device__ __align__(128) __nv_bfloat16 g_h2 [(size_t)MAX_NODES * HIDF];
__device__ __align__(128) __nv_bfloat16 g_g  [(size_t)MAX_NODES * OUTF];
__device__ __align__(128) float g_dinv[MAX_NODES];
__device__ __align__(128) int   g_cnt   [MAX_NODES];
__device__ __align__(128) int   g_rowptr[MAX_NODES + 1];
__device__ __align__(128) int   g_cursor[MAX_NODES];
__device__ __align__(128) int   g_adj   [MAX_EDGES];
__device__ __align__(128) int   g_bsum  [256];   // scan flags: aggregate+1, 0=unset
__device__ __align__(128) __nv_bfloat16 g_w2hi[HIDF * OUTF];
__device__ __align__(128) __nv_bfloat16 g_w2lo[HIDF * OUTF];

// ================= helpers ======================================================
__device__ __forceinline__ uint32_t smem_u32(const void* p) {
    uint32_t a;
    asm("{ .reg .u64 t; cvta.to.shared.u64 t, %1; cvt.u32.u64 %0, t; }" : "=r"(a) : "l"(p));
    return a;
}
__device__ __forceinline__ void ldsm_x4(uint32_t* r, uint32_t addr) {
    asm volatile("ldmatrix.sync.aligned.m8n8.x4.shared.b16 {%0,%1,%2,%3}, [%4];"
                 : "=r"(r[0]), "=r"(r[1]), "=r"(r[2]), "=r"(r[3]) : "r"(addr));
}
__device__ __forceinline__ void ldsm_x2(uint32_t* r, uint32_t addr) {
    asm volatile("ldmatrix.sync.aligned.m8n8.x2.shared.b16 {%0,%1}, [%2];"
                 : "=r"(r[0]), "=r"(r[1]) : "r"(addr));
}
__device__ __forceinline__ void mma_bf16(float* d, const uint32_t* a, const uint32_t* b) {
    asm volatile(
        "mma.sync.aligned.m16n8k16.row.col.f32.bf16.bf16.f32 "
        "{%0,%1,%2,%3}, {%4,%5,%6,%7}, {%8,%9}, {%0,%1,%2,%3};"
        : "+f"(d[0]), "+f"(d[1]), "+f"(d[2]), "+f"(d[3])
        : "r"(a[0]), "r"(a[1]), "r"(a[2]), "r"(a[3]), "r"(b[0]), "r"(b[1]));
}
__device__ __forceinline__ void mma_tf32(float* d, const uint32_t* a, const uint32_t* b) {
    asm volatile(
        "mma.sync.aligned.m16n8k8.row.col.f32.tf32.tf32.f32 "
        "{%0,%1,%2,%3}, {%4,%5,%6,%7}, {%8,%9}, {%0,%1,%2,%3};"
        : "+f"(d[0]), "+f"(d[1]), "+f"(d[2]), "+f"(d[3])
        : "r"(a[0]), "r"(a[1]), "r"(a[2]), "r"(a[3]), "r"(b[0]), "r"(b[1]));
}
__device__ __forceinline__ void cp16(uint32_t dst, const void* src, bool valid) {
    int sz = valid ? 16 : 0;
    asm volatile("cp.async.cg.shared.global [%0], [%1], 16, %2;"
                 :: "r"(dst), "l"(src), "r"(sz) : "memory");
}
#define CP_COMMIT() asm volatile("cp.async.commit_group;" ::: "memory")
#define CP_WAIT(n)  asm volatile("cp.async.wait_group %0;" :: "n"(n) : "memory")

__device__ __forceinline__ void bq8(const uint4& q, float* f) {
    f[0] = __uint_as_float(q.x << 16); f[1] = __uint_as_float(q.x & 0xffff0000u);
    f[2] = __uint_as_float(q.y << 16); f[3] = __uint_as_float(q.y & 0xffff0000u);
    f[4] = __uint_as_float(q.z << 16); f[5] = __uint_as_float(q.z & 0xffff0000u);
    f[6] = __uint_as_float(q.w << 16); f[7] = __uint_as_float(q.w & 0xffff0000u);
}
__device__ __forceinline__ void acc8(float* acc, const uint4& q, float nrm) {
    float f[8]; bq8(q, f);
    #pragma unroll
    for (int i = 0; i < 8; i++) acc[i] = fmaf(nrm, f[i], acc[i]);
}

// ================= CSR build ====================================================
__global__ void count_kernel(const int* __restrict__ dst, int E,
                             int* __restrict__ cnt, int* __restrict__ flags) {
    int i = blockIdx.x * blockDim.x + threadIdx.x;
    if (i < 256) flags[i] = 0;           // reset scan flags for this replay
    if (i < E) atomicAdd(&cnt[dst[i]], 1);
}

// single-kernel exclusive scan with decoupled aggregate flags.
// safe: blocks launch in index order, so predecessors are resident-or-done.
__global__ void csr_scan_kernel(const int* __restrict__ cnt, int n, int E,
                                int* __restrict__ rowptr, int* __restrict__ cursor,
                                float* __restrict__ dinv, int* __restrict__ flags) {
    const int b = blockIdx.x;
    const int i = b * SCAN_BS + threadIdx.x;
    const int c = (i < n) ? cnt[i] : 0;
    const int lane = threadIdx.x & 31, wid = threadIdx.x >> 5;

    // block-local inclusive scan
    int v = c;
    #pragma unroll
    for (int o = 1; o < 32; o <<= 1) {
        int t = __shfl_up_sync(~0u, v, o);
        if (lane >= o) v += t;
    }
    __shared__ int ws[32];
    if (lane == 31) ws[wid] = v;
    __syncthreads();
    if (threadIdx.x < 32) {
        int w = ws[threadIdx.x];
        #pragma unroll
        for (int o = 1; o < 32; o <<= 1) {
            int t = __shfl_up_sync(~0u, w, o);
            if ((int)threadIdx.x >= o) w += t;
        }
        ws[threadIdx.x] = w;
    }
    __syncthreads();
    const int tot = ws[31];

    // publish aggregate (+1 sentinel)
    if (threadIdx.x == 0) {
        __threadfence();
        atomicExch(&flags[b], tot + 1);
    }

    // lookback: sum aggregates of preceding blocks
    __shared__ int boff_sh;
    if (threadIdx.x < 32) {
        int s = 0;
        for (int j = (int)threadIdx.x; j < b; j += 32) {
            int f;
            do { f = atomicAdd(&flags[j], 0); } while (f == 0);
            s += f - 1;
        }
        #pragma unroll
        for (int o = 16; o > 0; o >>= 1) s += __shfl_xor_sync(~0u, s, o);
        if (threadIdx.x == 0) boff_sh = s;
    }
    __syncthreads();

    int excl = v - c + (wid > 0 ? ws[wid - 1] : 0) + boff_sh;
    if (i < n) {
        rowptr[i] = excl;
        cursor[i] = excl;
        dinv[i] = rsqrtf((float)c + 1.0f);
    }
    if (b == (int)gridDim.x - 1 && threadIdx.x == 0) rowptr[n] = E;
}

__global__ void fill_kernel(const int* __restrict__ src, const int* __restrict__ dst,
                            int E, int* __restrict__ cursor, int* __restrict__ adj) {
    int i = blockIdx.x * blockDim.x + threadIdx.x;
    if (i < E) {
        int pos = atomicAdd(&cursor[dst[i]], 1);
        adj[pos] = src[i];
    }
}

// ================= W2 prep ======================================================
__global__ void wsplit_kernel(const float* __restrict__ W, int K, int N,
                              __nv_bfloat16* __restrict__ hi, __nv_bfloat16* __restrict__ lo) {
    int idx = blockIdx.x * blockDim.x + threadIdx.x;
    if (idx >= K * N) return;
    int k = idx / N, n = idx % N;
    float w = W[(size_t)k * N + n];
    __nv_bfloat16 h = __float2bfloat16(w);
    __nv_bfloat16 l = __float2bfloat16(w - __bfloat162float(h));
    int c = k >> 6, kk = k & 63;
    uint32_t off = (uint32_t)(n * 128 + kk * 2);
    uint32_t sw = off ^ ((off >> 3) & 0x70);
    size_t pos = ((size_t)c * N * 128 + sw) / 2;
    hi[pos] = h;
    lo[pos] = l;
}

// ================= GEMM1: persistent tf32, inline W1 conversion ================
__global__ __launch_bounds__(512, 1)
void tf32_gemm(const float* __restrict__ A, int lda, const float* __restrict__ W1,
               __nv_bfloat16* __restrict__ C, int M, int ntiles)
{
    constexpr int NT  = HIDF;
    constexpr int KCH = 4;
    constexpr int BCH = NT * 256;
    constexpr int BB  = KCH * BCH;
    constexpr int OFF_A = BB;
    constexpr int ASTG = 32768;
    constexpr int NF  = 4;

    extern __shared__ char smraw[];
    char* sp = (char*)((((uintptr_t)smraw) + 1023) & ~(uintptr_t)1023);
    const uint32_t sb = smem_u32(sp);
    const uint32_t sbA = sb + OFF_A;

    const int tid = threadIdx.x;
    const int wid = tid >> 5;
    const int l   = tid & 31;
    const int warp_m = wid & 3;
    const int warp_n = wid >> 2;

    // W1 fp32 -> swizzled SMEM image, converted in-kernel (W1 stays L2-resident)
    for (int idx = tid; idx < INF * HIDF; idx += 512) {
        int k = idx >> 7;          // W1 row (K dim)
        int nn = idx & 127;        // W1 col (N dim)
        float w = W1[idx];
        int c = k >> 6, kk = k & 63;
        uint32_t off = (uint32_t)(nn * 256 + kk * 4);
        uint32_t sw = off ^ (((off >> 8) & 7) << 4);
        *(float*)(sp + c * BCH + sw) = w;
    }

    const uint32_t xorm = (uint32_t)(l & 7) << 4;
    const uint32_t aRow = warp_m * 32 + (l & 15);
    const uint32_t aK16 = (uint32_t)(l >> 4);
    const uint32_t bN   = warp_n * 32 + (l & 7);
    const uint32_t bK16 = (uint32_t)((l >> 3) & 1);
    const int g  = l >> 2;
    const int t2 = (l & 3) * 2;

    for (int tile = blockIdx.x; tile < ntiles; tile += gridDim.x) {
        const int blockRow = tile * 128;

        float acc[2][NF][4];
        #pragma unroll
        for (int i = 0; i < 2; i++)
            #pragma unroll
            for (int j = 0; j < NF; j++)
                #pragma unroll
                for (int q = 0; q < 4; q++) acc[i][j][q] = 0.f;

        #pragma unroll
        for (int v = 0; v < 4; v++) {
            int vid = tid + v * 512;
            int row = vid >> 4;
            int u   = vid & 15;
            int grow = blockRow + row;
            bool valid = grow < M;
            const float* src = A + (size_t)(valid ? grow : 0) * lda + u * 4;
            uint32_t dst = sbA + row * 256 + (((uint32_t)u * 16) ^ (((uint32_t)row & 7) << 4));
            cp16(dst, src, valid);
        }
        CP_COMMIT();
        if (tile == (int)blockIdx.x) __syncthreads();   // W1 image ready (first iter)

        for (int c = 0; c < KCH; c++) {
            const int buf = c & 1;
            if (c + 1 < KCH) {
                const int nb = (c + 1) & 1;
                #pragma unroll
                for (int v = 0; v < 4; v++) {
                    int vid = tid + v * 512;
                    int row = vid >> 4;
                    int u   = vid & 15;
                    int grow = blockRow + row;
                    bool valid = grow < M;
                    const float* src = A + (size_t)(valid ? grow : 0) * lda + (c + 1) * 64 + u * 4;
                    uint32_t dst = sbA + nb * ASTG + row * 256
                                 + (((uint32_t)u * 16) ^ (((uint32_t)row & 7) << 4));
                    cp16(dst, src, valid);
                }
                CP_COMMIT();
                CP_WAIT(1);
            } else {
                CP_WAIT(0);
            }
            __syncthreads();

            const uint32_t aB = sbA + buf * ASTG;
            const uint32_t bB = sb + c * BCH;
            #pragma unroll
            for (int s = 0; s < 8; s++) {
                const uint32_t koff = (uint32_t)s * 32;
                uint32_t bf[NF][2];
                #pragma unroll
                for (int j = 0; j < NF; j++)
                    ldsm_x2(bf[j], bB + (bN + j * 8) * 256 + ((koff + bK16 * 16) ^ xorm));
                #pragma unroll
                for (int i = 0; i < 2; i++) {
                    uint32_t af[4];
                    ldsm_x4(af, aB + (aRow + i * 16) * 256 + ((koff + aK16 * 16) ^ xorm));
                    #pragma unroll
                    for (int j = 0; j < NF; j++)
                        mma_tf32(acc[i][j], af, bf[j]);
                }
            }
            __syncthreads();
        }

        #pragma unroll
        for (int i = 0; i < 2; i++) {
            int row0 = blockRow + warp_m * 32 + i * 16 + g;
            #pragma unroll
            for (int j = 0; j < NF; j++) {
                int col = warp_n * 32 + j * 8 + t2;
                if (row0 < M) {
                    __nv_bfloat162 v = __floats2bfloat162_rn(acc[i][j][0], acc[i][j][1]);
                    *(__nv_bfloat162*)(C + (size_t)row0 * NT + col) = v;
                }
                if (row0 + 8 < M) {
                    __nv_bfloat162 v = __floats2bfloat162_rn(acc[i][j][2], acc[i][j][3]);
                    *(__nv_bfloat162*)(C + (size_t)(row0 + 8) * NT + col) = v;
                }
            }
        }
    }
}

// ================= GEMM2: persistent bf16 2-term, cp.async, 2 CTA/SM ===========
__global__ __launch_bounds__(256, 2)
void bf16_gemm(const __nv_bfloat16* __restrict__ A, int lda,
               const __nv_bfloat16* __restrict__ imgHi, const __nv_bfloat16* __restrict__ imgLo,
               __nv_bfloat16* __restrict__ C, int M, int ntiles)
{
    constexpr int NT  = OUTF;
    constexpr int KCH = 2;
    constexpr int BCH = NT * 128;
    constexpr int BB  = KCH * BCH;
    constexpr int OFF_BLO = BB;
    constexpr int OFF_A   = 2 * BB;
    constexpr int ASTG = 16384;
    constexpr int NTW = NT / 4;
    constexpr int NF  = NTW / 8;

    extern __shared__ char smraw[];
    char* sp = (char*)((((uintptr_t)smraw) + 1023) & ~(uintptr_t)1023);
    const uint32_t sb = smem_u32(sp);
    const uint32_t sbA = sb + OFF_A;

    const int tid = threadIdx.x;
    const int wid = tid >> 5;
    const int l   = tid & 31;
    const int warp_m = wid & 1;
    const int warp_n = wid >> 1;

    {
        const uint4* shi = (const uint4*)imgHi;
        const uint4* slo = (const uint4*)imgLo;
        uint4* dhi = (uint4*)sp;
        uint4* dlo = (uint4*)(sp + OFF_BLO);
        for (int i = tid; i < BB / 16; i += 256) { dhi[i] = shi[i]; dlo[i] = slo[i]; }
    }

    const uint32_t xorm = (uint32_t)(l & 7) << 4;
    const uint32_t aRow = warp_m * 64 + (l & 15);
    const uint32_t aK8  = (uint32_t)(l >> 4) * 8;
    const uint32_t bN   = warp_n * NTW + (l & 7);
    const uint32_t bK8  = (uint32_t)((l >> 3) & 1) * 8;
    const int g  = l >> 2;
    const int t2 = (l & 3) * 2;

    for (int tile = blockIdx.x; tile < ntiles; tile += gridDim.x) {
        const int blockRow = tile * 128;

        float acc[4][NF][4];
        #pragma unroll
        for (int i = 0; i < 4; i++)
            #pragma unroll
            for (int j = 0; j < NF; j++)
                #pragma unroll
                for (int q = 0; q < 4; q++) acc[i][j][q] = 0.f;

        #pragma unroll
        for (int v = 0; v < 4; v++) {
            int vid = tid + v * 256;
            int row = vid >> 3;
            int u   = vid & 7;
            int grow = blockRow + row;
            bool valid = grow < M;
            const __nv_bfloat16* src = A + (size_t)(valid ? grow : 0) * lda + u * 8;
            uint32_t dst = sbA + row * 128 + (((uint32_t)u * 16) ^ (((uint32_t)row & 7) << 4));
            cp16(dst, src, valid);
        }
        CP_COMMIT();

        for (int c = 0; c < KCH; c++) {
            const int buf = c & 1;
            if (c + 1 < KCH) {
                const int nb = (c + 1) & 1;
                #pragma unroll
                for (int v = 0; v < 4; v++) {
                    int vid = tid + v * 256;
                    int row = vid >> 3;
                    int u   = vid & 7;
                    int grow = blockRow + row;
                    bool valid = grow < M;
                    const __nv_bfloat16* src = A + (size_t)(valid ? grow : 0) * lda + (c + 1) * 64 + u * 8;
                    uint32_t dst = sbA + nb * ASTG + row * 128
                                 + (((uint32_t)u * 16) ^ (((uint32_t)row & 7) << 4));
                    cp16(dst, src, valid);
                }
                CP_COMMIT();
                CP_WAIT(1);
            } else {
                CP_WAIT(0);
            }
            __syncthreads();

            const uint32_t aB = sbA + buf * ASTG + aRow * 128;
            const uint32_t bHiBase = sb + c * BCH + bN * 128;
            const uint32_t bLoBase = bHiBase + OFF_BLO;
            #pragma unroll
            for (int s = 0; s < 4; s++) {
                const uint32_t akOff = ((uint32_t)(s * 16 + aK8) * 2) ^ xorm;
                const uint32_t bkOff = ((uint32_t)(s * 16 + bK8) * 2) ^ xorm;
                uint32_t bh[NF][2], bl[NF][2];
                #pragma unroll
                for (int j = 0; j < NF; j++) {
                    ldsm_x2(bh[j], bHiBase + j * 1024 + bkOff);
                    ldsm_x2(bl[j], bLoBase + j * 1024 + bkOff);
                }
                #pragma unroll
                for (int i = 0; i < 4; i++) {
                    uint32_t ah[4];
                    ldsm_x4(ah, aB + i * 2048 + akOff);
                    #pragma unroll
                    for (int j = 0; j < NF; j++) {
                        mma_bf16(acc[i][j], ah, bh[j]);
                        mma_bf16(acc[i][j], ah, bl[j]);
                    }
                }
            }
            __syncthreads();
        }

        #pragma unroll
        for (int i = 0; i < 4; i++) {
            int row0 = blockRow + warp_m * 64 + i * 16 + g;
            #pragma unroll
            for (int j = 0; j < NF; j++) {
                int col = warp_n * NTW + j * 8 + t2;
                if (row0 < M) {
                    __nv_bfloat162 v = __floats2bfloat162_rn(acc[i][j][0], acc[i][j][1]);
                    *(__nv_bfloat162*)(C + (size_t)row0 * NT + col) = v;
                }
                if (row0 + 8 < M) {
                    __nv_bfloat162 v = __floats2bfloat162_rn(acc[i][j][2], acc[i][j][3]);
                    *(__nv_bfloat162*)(C + (size_t)(row0 + 8) * NT + col) = v;
                }
            }
        }
    }
}

// ================= agg1: 16 lanes/node, uint4 loads, 4-edge unroll =============
__global__ void agg1_kernel(const __nv_bfloat16* __restrict__ h, const int* __restrict__ rowptr,
                            const int* __restrict__ adj, const float* __restrict__ dinv,
                            const float* __restrict__ b1, __nv_bfloat16* __restrict__ h2, int n)
{
    int node = (blockIdx.x * blockDim.x + threadIdx.x) >> 4;
    int sub  = threadIdx.x & 15;
    if (node >= n) return;
    int beg = rowptr[node], end = rowptr[node + 1];
    float dd = dinv[node];
    const size_t fo = (size_t)sub * 8;

    float acc[8];
    #pragma unroll
    for (int i = 0; i < 8; i++) acc[i] = 0.f;

    int e = beg;
    for (; e + 4 <= end; e += 4) {
        int s0 = __ldg(adj + e),     s1 = __ldg(adj + e + 1);
        int s2 = __ldg(adj + e + 2), s3 = __ldg(adj + e + 3);
        float n0 = __ldg(dinv + s0) * dd, n1 = __ldg(dinv + s1) * dd;
        float n2 = __ldg(dinv + s2) * dd, n3 = __ldg(dinv + s3) * dd;
        uint4 q0 = *(const uint4*)(h + (size_t)s0 * HIDF + fo);
        uint4 q1 = *(const uint4*)(h + (size_t)s1 * HIDF + fo);
        uint4 q2 = *(const uint4*)(h + (size_t)s2 * HIDF + fo);
        uint4 q3 = *(const uint4*)(h + (size_t)s3 * HIDF + fo);
        acc8(acc, q0, n0); acc8(acc, q1, n1); acc8(acc, q2, n2); acc8(acc, q3, n3);
    }
    for (; e < end; e++) {
        int s0 = __ldg(adj + e);
        float n0 = __ldg(dinv + s0) * dd;
        uint4 q0 = *(const uint4*)(h + (size_t)s0 * HIDF + fo);
        acc8(acc, q0, n0);
    }

    float d2 = dd * dd;
    uint4 qs = *(const uint4*)(h + (size_t)node * HIDF + fo);
    float sf[8]; bq8(qs, sf);
    float4 bv0 = *(const float4*)(b1 + fo);
    float4 bv1 = *(const float4*)(b1 + fo + 4);
    float bb[8] = {bv0.x, bv0.y, bv0.z, bv0.w, bv1.x, bv1.y, bv1.z, bv1.w};
    uint32_t o[4];
    #pragma unroll
    for (int i = 0; i < 4; i++) {
        float t0 = fmaf(d2, sf[2*i],   acc[2*i])   + bb[2*i];
        float t1 = fmaf(d2, sf[2*i+1], acc[2*i+1]) + bb[2*i+1];
        float r0 = 0.9f * fmaxf(t0, 0.f) + 0.1f;
        float r1 = 0.9f * fmaxf(t1, 0.f) + 0.1f;
        __nv_bfloat162 p = __floats2bfloat162_rn(r0, r1);
        o[i] = *reinterpret_cast<uint32_t*>(&p);
    }
    *(uint4*)(h2 + (size_t)node * HIDF + fo) = make_uint4(o[0], o[1], o[2], o[3]);
}

// ================= agg2: 8 lanes/node, uint4 loads, 4-edge unroll ==============
__global__ void agg2_kernel(const __nv_bfloat16* __restrict__ g, const int* __restrict__ rowptr,
                            const int* __restrict__ adj, const float* __restrict__ dinv,
                            const float* __restrict__ b2, float* __restrict__ out, int n)
{
    int node = (blockIdx.x * blockDim.x + threadIdx.x) >> 3;
    int sub  = threadIdx.x & 7;
    if (node >= n) return;
    int beg = rowptr[node], end = rowptr[node + 1];
    float dd = dinv[node];
    const size_t fo = (size_t)sub * 8;

    float acc[8];
    #pragma unroll
    for (int i = 0; i < 8; i++) acc[i] = 0.f;

    int e = beg;
    for (; e + 4 <= end; e += 4) {
        int s0 = __ldg(adj + e),     s1 = __ldg(adj + e + 1);
        int s2 = __ldg(adj + e + 2), s3 = __ldg(adj + e + 3);
        float n0 = __ldg(dinv + s0) * dd, n1 = __ldg(dinv + s1) * dd;
        float n2 = __ldg(dinv + s2) * dd, n3 = __ldg(dinv + s3) * dd;
        uint4 q0 = *(const uint4*)(g + (size_t)s0 * OUTF + fo);
        uint4 q1 = *(const uint4*)(g + (size_t)s1 * OUTF + fo);
        uint4 q2 = *(const uint4*)(g + (size_t)s2 * OUTF + fo);
        uint4 q3 = *(const uint4*)(g + (size_t)s3 * OUTF + fo);
        acc8(acc, q0, n0); acc8(acc, q1, n1); acc8(acc, q2, n2); acc8(acc, q3, n3);
    }
    for (; e < end; e++) {
        int s0 = __ldg(adj + e);
        float n0 = __ldg(dinv + s0) * dd;
        uint4 q0 = *(const uint4*)(g + (size_t)s0 * OUTF + fo);
        acc8(acc, q0, n0);
    }

    float d2 = dd * dd;
    uint4 qs = *(const uint4*)(g + (size_t)node * OUTF + fo);
    float sf[8]; bq8(qs, sf);
    float4 bv0 = *(const float4*)(b2 + fo);
    float4 bv1 = *(const float4*)(b2 + fo + 4);
    float bb[8] = {bv0.x, bv0.y, bv0.z, bv0.w, bv1.x, bv1.y, bv1.z, bv1.w};
    float v[8];
    #pragma unroll
    for (int i = 0; i < 8; i++) v[i] = fmaf(d2, sf[i], acc[i]) + bb[i];

    float m = v[0];
    #pragma unroll
    for (int i = 1; i < 8; i++) m = fmaxf(m, v[i]);
    #pragma unroll
    for (int o = 4; o > 0; o >>= 1) m = fmaxf(m, __shfl_xor_sync(~0u, m, o, 8));
    float s = 0.f;
    #pragma unroll
    for (int i = 0; i < 8; i++) s += expf(v[i] - m);
    #pragma unroll
    for (int o = 4; o > 0; o >>= 1) s += __shfl_xor_sync(~0u, s, o, 8);
    float ls = m + logf(s);

    float* op = out + (size_t)node * OUTF + fo;
    *(float4*)(op)     = make_float4(v[0]-ls, v[1]-ls, v[2]-ls, v[3]-ls);
    *(float4*)(op + 4) = make_float4(v[4]-ls, v[5]-ls, v[6]-ls, v[7]-ls);
}

// ================= launch =======================================================
extern "C" void kernel_launch(void* const* d_in, const int* in_sizes, int n_in,
                              void* d_out, int out_size)
{
    const float* x  = (const float*)d_in[0];
    const int*   ei = (const int*)  d_in[1];
    // d_in[2] edge_weight: unused (CRF softmax over singleton groups == 1.0)
    const float* W1 = (const float*)d_in[3];
    const float* b1 = (const float*)d_in[4];
    const float* W2 = (const float*)d_in[5];
    const float* b2 = (const float*)d_in[6];
    float* out = (float*)d_out;

    const int n = in_sizes[0] / INF;
    const int E = in_sizes[2];
    const int* src = ei;
    const int* dst = ei + E;

    __nv_bfloat16 *h, *h2, *g, *w2hi, *w2lo;
    float *dinv;
    int *cnt, *rowptr, *cursor, *adj, *bsum;
    cudaGetSymbolAddress((void**)&h,     g_h);
    cudaGetSymbolAddress((void**)&h2,    g_h2);
    cudaGetSymbolAddress((void**)&g,     g_g);
    cudaGetSymbolAddress((void**)&dinv,  g_dinv);
    cudaGetSymbolAddress((void**)&cnt,   g_cnt);
    cudaGetSymbolAddress((void**)&rowptr,g_rowptr);
    cudaGetSymbolAddress((void**)&cursor,g_cursor);
    cudaGetSymbolAddress((void**)&adj,   g_adj);
    cudaGetSymbolAddress((void**)&bsum,  g_bsum);
    cudaGetSymbolAddress((void**)&w2hi,  g_w2hi);
    cudaGetSymbolAddress((void**)&w2lo,  g_w2lo);

    const int nb = (n + SCAN_BS - 1) / SCAN_BS;
    const int mtiles = (n + 127) / 128;

    constexpr int SMEM1 = INF * HIDF * 4 + 2 * 32768 + 1024;
    constexpr int SMEM2 = 2 * (HIDF * OUTF * 2) + 2 * 16384 + 1024;
    cudaFuncSetAttribute(tf32_gemm, cudaFuncAttributeMaxDynamicSharedMemorySize, SMEM1);
    cudaFuncSetAttribute(bf16_gemm, cudaFuncAttributeMaxDynamicSharedMemorySize, SMEM2);

    static cudaStream_t sCsr = nullptr;
    static cudaEvent_t evFork = nullptr, evJoin = nullptr;
    if (!sCsr) {
        cudaStreamCreateWithFlags(&sCsr, cudaStreamNonBlocking);
        cudaEventCreateWithFlags(&evFork, cudaEventDisableTiming);
        cudaEventCreateWithFlags(&evJoin, cudaEventDisableTiming);
    }

    cudaEventRecord(evFork, 0);
    cudaStreamWaitEvent(sCsr, evFork, 0);

    // side stream: CSR build (count also resets scan flags) + W2 prep
    wsplit_kernel<<<(HIDF*OUTF + 255)/256, 256, 0, sCsr>>>(W2, HIDF, OUTF, w2hi, w2lo); // 1
    cudaMemsetAsync(cnt, 0, (size_t)n * sizeof(int), sCsr);                             // 2
    count_kernel<<<(E + 255)/256, 256, 0, sCsr>>>(dst, E, cnt, bsum);                   // 3
    csr_scan_kernel<<<nb, SCAN_BS, 0, sCsr>>>(cnt, n, E, rowptr, cursor, dinv, bsum);   // 4
    // main stream: GEMM1 (inline W1 conversion) — launch slot 5 for ncu
    tf32_gemm<<<148, 512, SMEM1>>>(x, INF, W1, h, n, mtiles);                           // 5
    fill_kernel<<<(E + 255)/256, 256, 0, sCsr>>>(src, dst, E, cursor, adj);             // 6
    cudaEventRecord(evJoin, sCsr);
    cudaStreamWaitEvent(0, evJoin, 0);

    agg1_kernel<<<((long long)n*16 + 255)/256, 256>>>(h, rowptr, adj, dinv, b1, h2, n);
    bf16_gemm<<<296, 256, SMEM2>>>(h2, HIDF, w2hi, w2lo, g, n, mtiles);
    agg2_kernel<<<((long long)n*8 + 255)/256, 256>>>(g, rowptr, adj, dinv, b2, out, n);
}

// round 12
// speedup vs baseline: 1.2290x; 1.0693x over previous
#include <cuda_runtime.h>
#include <cuda_bf16.h>
#include <cstdint>

#define MAX_NODES 100000
#define MAX_EDGES 1600000
#define INF  256
#define HIDF 128
#define OUTF 64
#define SCAN_BS 1024

// ---------------- device scratch ----------------------------------------------
__device__ __align__(128) __nv_bfloat16 g_h  [(size_t)MAX_NODES * HIDF];
__device__ __align__(128) __nv_bfloat16 g_h2 [(size_t)MAX_NODES * HIDF];
__device__ __align__(128) __nv_bfloat16 g_g  [(size_t)MAX_NODES * OUTF];
__device__ __align__(128) float g_dinv[MAX_NODES];
__device__ __align__(128) int   g_cnt   [MAX_NODES];
__device__ __align__(128) int   g_rowptr[MAX_NODES + 1];
__device__ __align__(128) int   g_cursor[MAX_NODES];
__device__ __align__(128) int   g_adj   [MAX_EDGES];
__device__ __align__(128) int   g_bsum  [256];
__device__ __align__(128) int   g_boff  [256];
__device__ __align__(128) float g_w1t [INF * HIDF];
__device__ __align__(128) __nv_bfloat16 g_w2hi[HIDF * OUTF];

// ================= helpers ======================================================
__device__ __forceinline__ uint32_t smem_u32(const void* p) {
    uint32_t a;
    asm("{ .reg .u64 t; cvta.to.shared.u64 t, %1; cvt.u32.u64 %0, t; }" : "=r"(a) : "l"(p));
    return a;
}
__device__ __forceinline__ void ldsm_x4(uint32_t* r, uint32_t addr) {
    asm volatile("ldmatrix.sync.aligned.m8n8.x4.shared.b16 {%0,%1,%2,%3}, [%4];"
                 : "=r"(r[0]), "=r"(r[1]), "=r"(r[2]), "=r"(r[3]) : "r"(addr));
}
__device__ __forceinline__ void ldsm_x2(uint32_t* r, uint32_t addr) {
    asm volatile("ldmatrix.sync.aligned.m8n8.x2.shared.b16 {%0,%1}, [%2];"
                 : "=r"(r[0]), "=r"(r[1]) : "r"(addr));
}
__device__ __forceinline__ void mma_bf16(float* d, const uint32_t* a, const uint32_t* b) {
    asm volatile(
        "mma.sync.aligned.m16n8k16.row.col.f32.bf16.bf16.f32 "
        "{%0,%1,%2,%3}, {%4,%5,%6,%7}, {%8,%9}, {%0,%1,%2,%3};"
        : "+f"(d[0]), "+f"(d[1]), "+f"(d[2]), "+f"(d[3])
        : "r"(a[0]), "r"(a[1]), "r"(a[2]), "r"(a[3]), "r"(b[0]), "r"(b[1]));
}
__device__ __forceinline__ void mma_tf32(float* d, const uint32_t* a, const uint32_t* b) {
    asm volatile(
        "mma.sync.aligned.m16n8k8.row.col.f32.tf32.tf32.f32 "
        "{%0,%1,%2,%3}, {%4,%5,%6,%7}, {%8,%9}, {%0,%1,%2,%3};"
        : "+f"(d[0]), "+f"(d[1]), "+f"(d[2]), "+f"(d[3])
        : "r"(a[0]), "r"(a[1]), "r"(a[2]), "r"(a[3]), "r"(b[0]), "r"(b[1]));
}
__device__ __forceinline__ void cp16(uint32_t dst, const void* src, bool valid) {
    int sz = valid ? 16 : 0;
    asm volatile("cp.async.cg.shared.global [%0], [%1], 16, %2;"
                 :: "r"(dst), "l"(src), "r"(sz) : "memory");
}
#define CP_COMMIT() asm volatile("cp.async.commit_group;" ::: "memory")
#define CP_WAIT(n)  asm volatile("cp.async.wait_group %0;" :: "n"(n) : "memory")

__device__ __forceinline__ void bq8(const uint4& q, float* f) {
    f[0] = __uint_as_float(q.x << 16); f[1] = __uint_as_float(q.x & 0xffff0000u);
    f[2] = __uint_as_float(q.y << 16); f[3] = __uint_as_float(q.y & 0xffff0000u);
    f[4] = __uint_as_float(q.z << 16); f[5] = __uint_as_float(q.z & 0xffff0000u);
    f[6] = __uint_as_float(q.w << 16); f[7] = __uint_as_float(q.w & 0xffff0000u);
}
__device__ __forceinline__ void acc8(float* acc, const uint4& q, float nrm) {
    float f[8]; bq8(q, f);
    #pragma unroll
    for (int i = 0; i < 8; i++) acc[i] = fmaf(nrm, f[i], acc[i]);
}

// ================= CSR build ====================================================
__global__ void count_kernel(const int* __restrict__ dst, int E, int* __restrict__ cnt) {
    int i = blockIdx.x * blockDim.x + threadIdx.x;
    if (i < E) atomicAdd(&cnt[dst[i]], 1);
}
__global__ void scanA_kernel(const int* __restrict__ cnt, int n, int* __restrict__ bsum) {
    int i = blockIdx.x * SCAN_BS + threadIdx.x;
    int c = (i < n) ? cnt[i] : 0;
    int lane = threadIdx.x & 31, wid = threadIdx.x >> 5;
    #pragma unroll
    for (int o = 16; o > 0; o >>= 1) c += __shfl_xor_sync(~0u, c, o);
    __shared__ int ws[32];
    if (lane == 0) ws[wid] = c;
    __syncthreads();
    if (threadIdx.x < 32) {
        int v = ws[threadIdx.x];
        #pragma unroll
        for (int o = 16; o > 0; o >>= 1) v += __shfl_xor_sync(~0u, v, o);
        if (threadIdx.x == 0) bsum[blockIdx.x] = v;
    }
}
__global__ void scanB_kernel(const int* __restrict__ bsum, int nb,
                             int* __restrict__ boff, int* __restrict__ rowptr,
                             int n, int E) {
    int t = threadIdx.x;
    int v = (t < nb) ? bsum[t] : 0;
    int lane = t & 31, w = t >> 5;
    int incl = v;
    #pragma unroll
    for (int o = 1; o < 32; o <<= 1) {
        int u = __shfl_up_sync(~0u, incl, o);
        if (lane >= o) incl += u;
    }
    __shared__ int ws[4];
    if (lane == 31) ws[w] = incl;
    __syncthreads();
    int add = 0;
    #pragma unroll
    for (int k = 0; k < 4; k++) if (k < w) add += ws[k];
    if (t < nb) boff[t] = incl - v + add;
    if (t == 0) rowptr[n] = E;
}
__global__ void scanC_kernel(const int* __restrict__ cnt, const int* __restrict__ boff,
                             int n, int* __restrict__ rowptr, int* __restrict__ cursor,
                             float* __restrict__ dinv) {
    int i = blockIdx.x * SCAN_BS + threadIdx.x;
    int c = (i < n) ? cnt[i] : 0;
    int lane = threadIdx.x & 31, wid = threadIdx.x >> 5;
    int v = c;
    #pragma unroll
    for (int o = 1; o < 32; o <<= 1) {
        int t = __shfl_up_sync(~0u, v, o);
        if (lane >= o) v += t;
    }
    __shared__ int ws[32];
    if (lane == 31) ws[wid] = v;
    __syncthreads();
    if (threadIdx.x < 32) {
        int w = ws[threadIdx.x];
        #pragma unroll
        for (int o = 1; o < 32; o <<= 1) {
            int t = __shfl_up_sync(~0u, w, o);
            if ((int)threadIdx.x >= o) w += t;
        }
        ws[threadIdx.x] = w;
    }
    __syncthreads();
    int excl = v - c + (wid > 0 ? ws[wid - 1] : 0) + boff[blockIdx.x];
    if (i < n) {
        rowptr[i] = excl;
        cursor[i] = excl;
        dinv[i] = rsqrtf((float)c + 1.0f);
    }
}
__global__ void fill_kernel(const int* __restrict__ src, const int* __restrict__ dst,
                            int E, int* __restrict__ cursor, int* __restrict__ adj) {
    int i = blockIdx.x * blockDim.x + threadIdx.x;
    if (i < E) {
        int pos = atomicAdd(&cursor[dst[i]], 1);
        adj[pos] = src[i];
    }
}

// ================= weight prep ==================================================
__global__ void wtf32_kernel(const float* __restrict__ W, int K, int N,
                             float* __restrict__ img) {
    int idx = blockIdx.x * blockDim.x + threadIdx.x;
    if (idx >= K * N) return;
    int k = idx / N, n = idx % N;
    int c = k >> 6, kk = k & 63;
    uint32_t off = (uint32_t)(n * 256 + kk * 4);
    uint32_t sw = off ^ (((off >> 8) & 7) << 4);
    img[((size_t)c * N * 256 + sw) / 4] = W[(size_t)k * N + n];
}
// W2 -> bf16 (single image, 1-term)
__global__ void wbf16_kernel(const float* __restrict__ W, int K, int N,
                             __nv_bfloat16* __restrict__ hi) {
    int idx = blockIdx.x * blockDim.x + threadIdx.x;
    if (idx >= K * N) return;
    int k = idx / N, n = idx % N;
    __nv_bfloat16 h = __float2bfloat16(W[(size_t)k * N + n]);
    int c = k >> 6, kk = k & 63;
    uint32_t off = (uint32_t)(n * 128 + kk * 2);
    uint32_t sw = off ^ ((off >> 3) & 0x70);
    hi[((size_t)c * N * 128 + sw) / 2] = h;
}

// ================= GEMM1: persistent tf32, 512 threads, cp.async ==============
__global__ __launch_bounds__(512, 1)
void tf32_gemm(const float* __restrict__ A, int lda, const float* __restrict__ img,
               __nv_bfloat16* __restrict__ C, int M, int ntiles)
{
    constexpr int NT  = HIDF;
    constexpr int KCH = 4;
    constexpr int BCH = NT * 256;
    constexpr int BB  = KCH * BCH;
    constexpr int OFF_A = BB;
    constexpr int ASTG = 32768;
    constexpr int NF  = 4;

    extern __shared__ char smraw[];
    char* sp = (char*)((((uintptr_t)smraw) + 1023) & ~(uintptr_t)1023);
    const uint32_t sb = smem_u32(sp);
    const uint32_t sbA = sb + OFF_A;

    const int tid = threadIdx.x;
    const int wid = tid >> 5;
    const int l   = tid & 31;
    const int warp_m = wid & 3;
    const int warp_n = wid >> 2;

    {
        const uint4* s = (const uint4*)img;
        uint4* d = (uint4*)sp;
        for (int i = tid; i < BB / 16; i += 512) d[i] = s[i];
    }

    const uint32_t xorm = (uint32_t)(l & 7) << 4;
    const uint32_t aRow = warp_m * 32 + (l & 15);
    const uint32_t aK16 = (uint32_t)(l >> 4);
    const uint32_t bN   = warp_n * 32 + (l & 7);
    const uint32_t bK16 = (uint32_t)((l >> 3) & 1);
    const int g  = l >> 2;
    const int t2 = (l & 3) * 2;

    for (int tile = blockIdx.x; tile < ntiles; tile += gridDim.x) {
        const int blockRow = tile * 128;

        float acc[2][NF][4];
        #pragma unroll
        for (int i = 0; i < 2; i++)
            #pragma unroll
            for (int j = 0; j < NF; j++)
                #pragma unroll
                for (int q = 0; q < 4; q++) acc[i][j][q] = 0.f;

        #pragma unroll
        for (int v = 0; v < 4; v++) {
            int vid = tid + v * 512;
            int row = vid >> 4;
            int u   = vid & 15;
            int grow = blockRow + row;
            bool valid = grow < M;
            const float* src = A + (size_t)(valid ? grow : 0) * lda + u * 4;
            uint32_t dst = sbA + row * 256 + (((uint32_t)u * 16) ^ (((uint32_t)row & 7) << 4));
            cp16(dst, src, valid);
        }
        CP_COMMIT();

        for (int c = 0; c < KCH; c++) {
            const int buf = c & 1;
            if (c + 1 < KCH) {
                const int nb = (c + 1) & 1;
                #pragma unroll
                for (int v = 0; v < 4; v++) {
                    int vid = tid + v * 512;
                    int row = vid >> 4;
                    int u   = vid & 15;
                    int grow = blockRow + row;
                    bool valid = grow < M;
                    const float* src = A + (size_t)(valid ? grow : 0) * lda + (c + 1) * 64 + u * 4;
                    uint32_t dst = sbA + nb * ASTG + row * 256
                                 + (((uint32_t)u * 16) ^ (((uint32_t)row & 7) << 4));
                    cp16(dst, src, valid);
                }
                CP_COMMIT();
                CP_WAIT(1);
            } else {
                CP_WAIT(0);
            }
            __syncthreads();

            const uint32_t aB = sbA + buf * ASTG;
            const uint32_t bB = sb + c * BCH;
            #pragma unroll
            for (int s = 0; s < 8; s++) {
                const uint32_t koff = (uint32_t)s * 32;
                uint32_t bf[NF][2];
                #pragma unroll
                for (int j = 0; j < NF; j++)
                    ldsm_x2(bf[j], bB + (bN + j * 8) * 256 + ((koff + bK16 * 16) ^ xorm));
                #pragma unroll
                for (int i = 0; i < 2; i++) {
                    uint32_t af[4];
                    ldsm_x4(af, aB + (aRow + i * 16) * 256 + ((koff + aK16 * 16) ^ xorm));
                    #pragma unroll
                    for (int j = 0; j < NF; j++)
                        mma_tf32(acc[i][j], af, bf[j]);
                }
            }
            __syncthreads();
        }

        #pragma unroll
        for (int i = 0; i < 2; i++) {
            int row0 = blockRow + warp_m * 32 + i * 16 + g;
            #pragma unroll
            for (int j = 0; j < NF; j++) {
                int col = warp_n * 32 + j * 8 + t2;
                if (row0 < M) {
                    __nv_bfloat162 v = __floats2bfloat162_rn(acc[i][j][0], acc[i][j][1]);
                    *(__nv_bfloat162*)(C + (size_t)row0 * NT + col) = v;
                }
                if (row0 + 8 < M) {
                    __nv_bfloat162 v = __floats2bfloat162_rn(acc[i][j][2], acc[i][j][3]);
                    *(__nv_bfloat162*)(C + (size_t)(row0 + 8) * NT + col) = v;
                }
            }
        }
    }
}

// ================= GEMM2: persistent bf16 1-term, cp.async, 4 CTA/SM ===========
__global__ __launch_bounds__(256, 4)
void bf16_gemm(const __nv_bfloat16* __restrict__ A, int lda,
               const __nv_bfloat16* __restrict__ imgHi,
               __nv_bfloat16* __restrict__ C, int M, int ntiles)
{
    constexpr int NT  = OUTF;
    constexpr int KCH = 2;
    constexpr int BCH = NT * 128;     // 8KB per chunk
    constexpr int BB  = KCH * BCH;    // 16KB weights
    constexpr int OFF_A = BB;
    constexpr int ASTG = 16384;
    constexpr int NTW = NT / 4;
    constexpr int NF  = NTW / 8;

    extern __shared__ char smraw[];
    char* sp = (char*)((((uintptr_t)smraw) + 1023) & ~(uintptr_t)1023);
    const uint32_t sb = smem_u32(sp);
    const uint32_t sbA = sb + OFF_A;

    const int tid = threadIdx.x;
    const int wid = tid >> 5;
    const int l   = tid & 31;
    const int warp_m = wid & 1;
    const int warp_n = wid >> 1;

    {
        const uint4* shi = (const uint4*)imgHi;
        uint4* dhi = (uint4*)sp;
        for (int i = tid; i < BB / 16; i += 256) dhi[i] = shi[i];
    }

    const uint32_t xorm = (uint32_t)(l & 7) << 4;
    const uint32_t aRow = warp_m * 64 + (l & 15);
    const uint32_t aK8  = (uint32_t)(l >> 4) * 8;
    const uint32_t bN   = warp_n * NTW + (l & 7);
    const uint32_t bK8  = (uint32_t)((l >> 3) & 1) * 8;
    const int g  = l >> 2;
    const int t2 = (l & 3) * 2;

    for (int tile = blockIdx.x; tile < ntiles; tile += gridDim.x) {
        const int blockRow = tile * 128;

        float acc[4][NF][4];
        #pragma unroll
        for (int i = 0; i < 4; i++)
            #pragma unroll
            for (int j = 0; j < NF; j++)
                #pragma unroll
                for (int q = 0; q < 4; q++) acc[i][j][q] = 0.f;

        #pragma unroll
        for (int v = 0; v < 4; v++) {
            int vid = tid + v * 256;
            int row = vid >> 3;
            int u   = vid & 7;
            int grow = blockRow + row;
            bool valid = grow < M;
            const __nv_bfloat16* src = A + (size_t)(valid ? grow : 0) * lda + u * 8;
            uint32_t dst = sbA + row * 128 + (((uint32_t)u * 16) ^ (((uint32_t)row & 7) << 4));
            cp16(dst, src, valid);
        }
        CP_COMMIT();

        for (int c = 0; c < KCH; c++) {
            const int buf = c & 1;
            if (c + 1 < KCH) {
                const int nb = (c + 1) & 1;
                #pragma unroll
                for (int v = 0; v < 4; v++) {
                    int vid = tid + v * 256;
                    int row = vid >> 3;
                    int u   = vid & 7;
                    int grow = blockRow + row;
                    bool valid = grow < M;
                    const __nv_bfloat16* src = A + (size_t)(valid ? grow : 0) * lda + (c + 1) * 64 + u * 8;
                    uint32_t dst = sbA + nb * ASTG + row * 128
                                 + (((uint32_t)u * 16) ^ (((uint32_t)row & 7) << 4));
                    cp16(dst, src, valid);
                }
                CP_COMMIT();
                CP_WAIT(1);
            } else {
                CP_WAIT(0);
            }
            __syncthreads();

            const uint32_t aB = sbA + buf * ASTG + aRow * 128;
            const uint32_t bHiBase = sb + c * BCH + bN * 128;
            #pragma unroll
            for (int s = 0; s < 4; s++) {
                const uint32_t akOff = ((uint32_t)(s * 16 + aK8) * 2) ^ xorm;
                const uint32_t bkOff = ((uint32_t)(s * 16 + bK8) * 2) ^ xorm;
                uint32_t bh[NF][2];
                #pragma unroll
                for (int j = 0; j < NF; j++)
                    ldsm_x2(bh[j], bHiBase + j * 1024 + bkOff);
                #pragma unroll
                for (int i = 0; i < 4; i++) {
                    uint32_t ah[4];
                    ldsm_x4(ah, aB + i * 2048 + akOff);
                    #pragma unroll
                    for (int j = 0; j < NF; j++)
                        mma_bf16(acc[i][j], ah, bh[j]);
                }
            }
            __syncthreads();
        }

        #pragma unroll
        for (int i = 0; i < 4; i++) {
            int row0 = blockRow + warp_m * 64 + i * 16 + g;
            #pragma unroll
            for (int j = 0; j < NF; j++) {
                int col = warp_n * NTW + j * 8 + t2;
                if (row0 < M) {
                    __nv_bfloat162 v = __floats2bfloat162_rn(acc[i][j][0], acc[i][j][1]);
                    *(__nv_bfloat162*)(C + (size_t)row0 * NT + col) = v;
                }
                if (row0 + 8 < M) {
                    __nv_bfloat162 v = __floats2bfloat162_rn(acc[i][j][2], acc[i][j][3]);
                    *(__nv_bfloat162*)(C + (size_t)(row0 + 8) * NT + col) = v;
                }
            }
        }
    }
}

// ================= agg1: 16 lanes/node, uint4 loads, 4-edge unroll =============
__global__ void agg1_kernel(const __nv_bfloat16* __restrict__ h, const int* __restrict__ rowptr,
                            const int* __restrict__ adj, const float* __restrict__ dinv,
                            const float* __restrict__ b1, __nv_bfloat16* __restrict__ h2, int n)
{
    int node = (blockIdx.x * blockDim.x + threadIdx.x) >> 4;
    int sub  = threadIdx.x & 15;
    if (node >= n) return;
    int beg = rowptr[node], end = rowptr[node + 1];
    float dd = dinv[node];
    const size_t fo = (size_t)sub * 8;

    float acc[8];
    #pragma unroll
    for (int i = 0; i < 8; i++) acc[i] = 0.f;

    int e = beg;
    for (; e + 4 <= end; e += 4) {
        int s0 = __ldg(adj + e),     s1 = __ldg(adj + e + 1);
        int s2 = __ldg(adj + e + 2), s3 = __ldg(adj + e + 3);
        float n0 = __ldg(dinv + s0) * dd, n1 = __ldg(dinv + s1) * dd;
        float n2 = __ldg(dinv + s2) * dd, n3 = __ldg(dinv + s3) * dd;
        uint4 q0 = *(const uint4*)(h + (size_t)s0 * HIDF + fo);
        uint4 q1 = *(const uint4*)(h + (size_t)s1 * HIDF + fo);
        uint4 q2 = *(const uint4*)(h + (size_t)s2 * HIDF + fo);
        uint4 q3 = *(const uint4*)(h + (size_t)s3 * HIDF + fo);
        acc8(acc, q0, n0); acc8(acc, q1, n1); acc8(acc, q2, n2); acc8(acc, q3, n3);
    }
    for (; e < end; e++) {
        int s0 = __ldg(adj + e);
        float n0 = __ldg(dinv + s0) * dd;
        uint4 q0 = *(const uint4*)(h + (size_t)s0 * HIDF + fo);
        acc8(acc, q0, n0);
    }

    float d2 = dd * dd;
    uint4 qs = *(const uint4*)(h + (size_t)node * HIDF + fo);
    float sf[8]; bq8(qs, sf);
    float4 bv0 = *(const float4*)(b1 + fo);
    float4 bv1 = *(const float4*)(b1 + fo + 4);
    float bb[8] = {bv0.x, bv0.y, bv0.z, bv0.w, bv1.x, bv1.y, bv1.z, bv1.w};
    uint32_t o[4];
    #pragma unroll
    for (int i = 0; i < 4; i++) {
        float t0 = fmaf(d2, sf[2*i],   acc[2*i])   + bb[2*i];
        float t1 = fmaf(d2, sf[2*i+1], acc[2*i+1]) + bb[2*i+1];
        float r0 = 0.9f * fmaxf(t0, 0.f) + 0.1f;
        float r1 = 0.9f * fmaxf(t1, 0.f) + 0.1f;
        __nv_bfloat162 p = __floats2bfloat162_rn(r0, r1);
        o[i] = *reinterpret_cast<uint32_t*>(&p);
    }
    *(uint4*)(h2 + (size_t)node * HIDF + fo) = make_uint4(o[0], o[1], o[2], o[3]);
}

// ================= agg2: 8 lanes/node, uint4 loads, 4-edge unroll ==============
__global__ void agg2_kernel(const __nv_bfloat16* __restrict__ g, const int* __restrict__ rowptr,
                            const int* __restrict__ adj, const float* __restrict__ dinv,
                            const float* __restrict__ b2, float* __restrict__ out, int n)
{
    int node = (blockIdx.x * blockDim.x + threadIdx.x) >> 3;
    int sub  = threadIdx.x & 7;
    if (node >= n) return;
    int beg = rowptr[node], end = rowptr[node + 1];
    float dd = dinv[node];
    const size_t fo = (size_t)sub * 8;

    float acc[8];
    #pragma unroll
    for (int i = 0; i < 8; i++) acc[i] = 0.f;

    int e = beg;
    for (; e + 4 <= end; e += 4) {
        int s0 = __ldg(adj + e),     s1 = __ldg(adj + e + 1);
        int s2 = __ldg(adj + e + 2), s3 = __ldg(adj + e + 3);
        float n0 = __ldg(dinv + s0) * dd, n1 = __ldg(dinv + s1) * dd;
        float n2 = __ldg(dinv + s2) * dd, n3 = __ldg(dinv + s3) * dd;
        uint4 q0 = *(const uint4*)(g + (size_t)s0 * OUTF + fo);
        uint4 q1 = *(const uint4*)(g + (size_t)s1 * OUTF + fo);
        uint4 q2 = *(const uint4*)(g + (size_t)s2 * OUTF + fo);
        uint4 q3 = *(const uint4*)(g + (size_t)s3 * OUTF + fo);
        acc8(acc, q0, n0); acc8(acc, q1, n1); acc8(acc, q2, n2); acc8(acc, q3, n3);
    }
    for (; e < end; e++) {
        int s0 = __ldg(adj + e);
        float n0 = __ldg(dinv + s0) * dd;
        uint4 q0 = *(const uint4*)(g + (size_t)s0 * OUTF + fo);
        acc8(acc, q0, n0);
    }

    float d2 = dd * dd;
    uint4 qs = *(const uint4*)(g + (size_t)node * OUTF + fo);
    float sf[8]; bq8(qs, sf);
    float4 bv0 = *(const float4*)(b2 + fo);
    float4 bv1 = *(const float4*)(b2 + fo + 4);
    float bb[8] = {bv0.x, bv0.y, bv0.z, bv0.w, bv1.x, bv1.y, bv1.z, bv1.w};
    float v[8];
    #pragma unroll
    for (int i = 0; i < 8; i++) v[i] = fmaf(d2, sf[i], acc[i]) + bb[i];

    float m = v[0];
    #pragma unroll
    for (int i = 1; i < 8; i++) m = fmaxf(m, v[i]);
    #pragma unroll
    for (int o = 4; o > 0; o >>= 1) m = fmaxf(m, __shfl_xor_sync(~0u, m, o, 8));
    float s = 0.f;
    #pragma unroll
    for (int i = 0; i < 8; i++) s += expf(v[i] - m);
    #pragma unroll
    for (int o = 4; o > 0; o >>= 1) s += __shfl_xor_sync(~0u, s, o, 8);
    float ls = m + logf(s);

    float* op = out + (size_t)node * OUTF + fo;
    *(float4*)(op)     = make_float4(v[0]-ls, v[1]-ls, v[2]-ls, v[3]-ls);
    *(float4*)(op + 4) = make_float4(v[4]-ls, v[5]-ls, v[6]-ls, v[7]-ls);
}

// ================= launch =======================================================
extern "C" void kernel_launch(void* const* d_in, const int* in_sizes, int n_in,
                              void* d_out, int out_size)
{
    const float* x  = (const float*)d_in[0];
    const int*   ei = (const int*)  d_in[1];
    // d_in[2] edge_weight: unused (CRF softmax over singleton groups == 1.0)
    const float* W1 = (const float*)d_in[3];
    const float* b1 = (const float*)d_in[4];
    const float* W2 = (const float*)d_in[5];
    const float* b2 = (const float*)d_in[6];
    float* out = (float*)d_out;

    const int n = in_sizes[0] / INF;
    const int E = in_sizes[2];
    const int* src = ei;
    const int* dst = ei + E;

    __nv_bfloat16 *h, *h2, *g, *w2hi;
    float *dinv, *w1t;
    int *cnt, *rowptr, *cursor, *adj, *bsum, *boff;
    cudaGetSymbolAddress((void**)&h,     g_h);
    cudaGetSymbolAddress((void**)&h2,    g_h2);
    cudaGetSymbolAddress((void**)&g,     g_g);
    cudaGetSymbolAddress((void**)&dinv,  g_dinv);
    cudaGetSymbolAddress((void**)&cnt,   g_cnt);
    cudaGetSymbolAddress((void**)&rowptr,g_rowptr);
    cudaGetSymbolAddress((void**)&cursor,g_cursor);
    cudaGetSymbolAddress((void**)&adj,   g_adj);
    cudaGetSymbolAddress((void**)&bsum,  g_bsum);
    cudaGetSymbolAddress((void**)&boff,  g_boff);
    cudaGetSymbolAddress((void**)&w1t,   g_w1t);
    cudaGetSymbolAddress((void**)&w2hi,  g_w2hi);

    const int nb = (n + SCAN_BS - 1) / SCAN_BS;
    const int mtiles = (n + 127) / 128;

    constexpr int SMEM1 = INF * HIDF * 4 + 2 * 32768 + 1024;
    constexpr int SMEM2 = HIDF * OUTF * 2 + 2 * 16384 + 1024;  // 16K wts + 32K A + pad
    cudaFuncSetAttribute(tf32_gemm, cudaFuncAttributeMaxDynamicSharedMemorySize, SMEM1);
    cudaFuncSetAttribute(bf16_gemm, cudaFuncAttributeMaxDynamicSharedMemorySize, SMEM2);

    static cudaStream_t sCsr = nullptr;
    static cudaEvent_t evFork = nullptr, evJoin = nullptr;
    if (!sCsr) {
        cudaStreamCreateWithFlags(&sCsr, cudaStreamNonBlocking);
        cudaEventCreateWithFlags(&evFork, cudaEventDisableTiming);
        cudaEventCreateWithFlags(&evJoin, cudaEventDisableTiming);
    }

    cudaEventRecord(evFork, 0);
    cudaStreamWaitEvent(sCsr, evFork, 0);

    // submission order puts tf32_gemm at launch slot 5 for ncu (-s 5):
    cudaMemsetAsync(cnt, 0, (size_t)n * sizeof(int), sCsr);                     // 1
    count_kernel<<<(E + 255)/256, 256, 0, sCsr>>>(dst, E, cnt);                 // 2
    scanA_kernel<<<nb, SCAN_BS, 0, sCsr>>>(cnt, n, bsum);                       // 3
    wtf32_kernel<<<(INF*HIDF + 255)/256, 256>>>(W1, INF, HIDF, w1t);            // 4
    tf32_gemm<<<148, 512, SMEM1>>>(x, INF, w1t, h, n, mtiles);                  // 5
    scanB_kernel<<<1, 128, 0, sCsr>>>(bsum, nb, boff, rowptr, n, E);            // 6
    scanC_kernel<<<nb, SCAN_BS, 0, sCsr>>>(cnt, boff, n, rowptr, cursor, dinv); // 7
    fill_kernel <<<(E + 255)/256, 256, 0, sCsr>>>(src, dst, E, cursor, adj);    // 8
    wbf16_kernel<<<(HIDF*OUTF + 255)/256, 256, 0, sCsr>>>(W2, HIDF, OUTF, w2hi);
    cudaEventRecord(evJoin, sCsr);
    cudaStreamWaitEvent(0, evJoin, 0);

    agg1_kernel<<<((long long)n*16 + 255)/256, 256>>>(h, rowptr, adj, dinv, b1, h2, n);
    bf16_gemm<<<592, 256, SMEM2>>>(h2, HIDF, w2hi, g, n, mtiles);
    agg2_kernel<<<((long long)n*8 + 255)/256, 256>>>(g, rowptr, adj, dinv, b2, out, n);
}

// round 13
// speedup vs baseline: 1.3070x; 1.0634x over previous
#include <cuda_runtime.h>
#include <cuda_bf16.h>
#include <cstdint>

#define MAX_NODES 100000
#define MAX_EDGES 1600000
#define INF  256
#define HIDF 128
#define OUTF 64
#define SCAN_BS 1024

// ---------------- device scratch ----------------------------------------------
__device__ __align__(128) __nv_bfloat16 g_h  [(size_t)MAX_NODES * HIDF];
__device__ __align__(128) __nv_bfloat16 g_h2 [(size_t)MAX_NODES * HIDF];
__device__ __align__(128) __nv_bfloat16 g_g  [(size_t)MAX_NODES * OUTF];
__device__ __align__(128) float g_dinv[MAX_NODES];
__device__ __align__(128) int   g_cnt   [MAX_NODES];
__device__ __align__(128) int   g_rowptr[MAX_NODES + 1];
__device__ __align__(128) int   g_cursor[MAX_NODES];
__device__ __align__(128) int   g_adj   [MAX_EDGES];
__device__ __align__(128) int   g_bsum  [256];
__device__ __align__(128) int   g_boff  [256];
__device__ __align__(128) __nv_bfloat16 g_w1hi[INF * HIDF];   // W1 bf16 image
__device__ __align__(128) __nv_bfloat16 g_w2hi[HIDF * OUTF];  // W2 bf16 image

// ================= helpers ======================================================
__device__ __forceinline__ uint32_t smem_u32(const void* p) {
    uint32_t a;
    asm("{ .reg .u64 t; cvta.to.shared.u64 t, %1; cvt.u32.u64 %0, t; }" : "=r"(a) : "l"(p));
    return a;
}
__device__ __forceinline__ void ldsm_x4(uint32_t* r, uint32_t addr) {
    asm volatile("ldmatrix.sync.aligned.m8n8.x4.shared.b16 {%0,%1,%2,%3}, [%4];"
                 : "=r"(r[0]), "=r"(r[1]), "=r"(r[2]), "=r"(r[3]) : "r"(addr));
}
__device__ __forceinline__ void ldsm_x2(uint32_t* r, uint32_t addr) {
    asm volatile("ldmatrix.sync.aligned.m8n8.x2.shared.b16 {%0,%1}, [%2];"
                 : "=r"(r[0]), "=r"(r[1]) : "r"(addr));
}
__device__ __forceinline__ void mma_bf16(float* d, const uint32_t* a, const uint32_t* b) {
    asm volatile(
        "mma.sync.aligned.m16n8k16.row.col.f32.bf16.bf16.f32 "
        "{%0,%1,%2,%3}, {%4,%5,%6,%7}, {%8,%9}, {%0,%1,%2,%3};"
        : "+f"(d[0]), "+f"(d[1]), "+f"(d[2]), "+f"(d[3])
        : "r"(a[0]), "r"(a[1]), "r"(a[2]), "r"(a[3]), "r"(b[0]), "r"(b[1]));
}
__device__ __forceinline__ void cp16(uint32_t dst, const void* src, bool valid) {
    int sz = valid ? 16 : 0;
    asm volatile("cp.async.cg.shared.global [%0], [%1], 16, %2;"
                 :: "r"(dst), "l"(src), "r"(sz) : "memory");
}
#define CP_COMMIT() asm volatile("cp.async.commit_group;" ::: "memory")
#define CP_WAIT(n)  asm volatile("cp.async.wait_group %0;" :: "n"(n) : "memory")

__device__ __forceinline__ void bq8(const uint4& q, float* f) {
    f[0] = __uint_as_float(q.x << 16); f[1] = __uint_as_float(q.x & 0xffff0000u);
    f[2] = __uint_as_float(q.y << 16); f[3] = __uint_as_float(q.y & 0xffff0000u);
    f[4] = __uint_as_float(q.z << 16); f[5] = __uint_as_float(q.z & 0xffff0000u);
    f[6] = __uint_as_float(q.w << 16); f[7] = __uint_as_float(q.w & 0xffff0000u);
}
__device__ __forceinline__ void acc8(float* acc, const uint4& q, float nrm) {
    float f[8]; bq8(q, f);
    #pragma unroll
    for (int i = 0; i < 8; i++) acc[i] = fmaf(nrm, f[i], acc[i]);
}

// ================= CSR build ====================================================
__global__ void count_kernel(const int* __restrict__ dst, int E, int* __restrict__ cnt) {
    int i = blockIdx.x * blockDim.x + threadIdx.x;
    if (i < E) atomicAdd(&cnt[dst[i]], 1);
}
__global__ void scanA_kernel(const int* __restrict__ cnt, int n, int* __restrict__ bsum) {
    int i = blockIdx.x * SCAN_BS + threadIdx.x;
    int c = (i < n) ? cnt[i] : 0;
    int lane = threadIdx.x & 31, wid = threadIdx.x >> 5;
    #pragma unroll
    for (int o = 16; o > 0; o >>= 1) c += __shfl_xor_sync(~0u, c, o);
    __shared__ int ws[32];
    if (lane == 0) ws[wid] = c;
    __syncthreads();
    if (threadIdx.x < 32) {
        int v = ws[threadIdx.x];
        #pragma unroll
        for (int o = 16; o > 0; o >>= 1) v += __shfl_xor_sync(~0u, v, o);
        if (threadIdx.x == 0) bsum[blockIdx.x] = v;
    }
}
__global__ void scanB_kernel(const int* __restrict__ bsum, int nb,
                             int* __restrict__ boff, int* __restrict__ rowptr,
                             int n, int E) {
    int t = threadIdx.x;
    int v = (t < nb) ? bsum[t] : 0;
    int lane = t & 31, w = t >> 5;
    int incl = v;
    #pragma unroll
    for (int o = 1; o < 32; o <<= 1) {
        int u = __shfl_up_sync(~0u, incl, o);
        if (lane >= o) incl += u;
    }
    __shared__ int ws[4];
    if (lane == 31) ws[w] = incl;
    __syncthreads();
    int add = 0;
    #pragma unroll
    for (int k = 0; k < 4; k++) if (k < w) add += ws[k];
    if (t < nb) boff[t] = incl - v + add;
    if (t == 0) rowptr[n] = E;
}
__global__ void scanC_kernel(const int* __restrict__ cnt, const int* __restrict__ boff,
                             int n, int* __restrict__ rowptr, int* __restrict__ cursor,
                             float* __restrict__ dinv) {
    int i = blockIdx.x * SCAN_BS + threadIdx.x;
    int c = (i < n) ? cnt[i] : 0;
    int lane = threadIdx.x & 31, wid = threadIdx.x >> 5;
    int v = c;
    #pragma unroll
    for (int o = 1; o < 32; o <<= 1) {
        int t = __shfl_up_sync(~0u, v, o);
        if (lane >= o) v += t;
    }
    __shared__ int ws[32];
    if (lane == 31) ws[wid] = v;
    __syncthreads();
    if (threadIdx.x < 32) {
        int w = ws[threadIdx.x];
        #pragma unroll
        for (int o = 1; o < 32; o <<= 1) {
            int t = __shfl_up_sync(~0u, w, o);
            if ((int)threadIdx.x >= o) w += t;
        }
        ws[threadIdx.x] = w;
    }
    __syncthreads();
    int excl = v - c + (wid > 0 ? ws[wid - 1] : 0) + boff[blockIdx.x];
    if (i < n) {
        rowptr[i] = excl;
        cursor[i] = excl;
        dinv[i] = rsqrtf((float)c + 1.0f);
    }
}
__global__ void fill_kernel(const int* __restrict__ src, const int* __restrict__ dst,
                            int E, int* __restrict__ cursor, int* __restrict__ adj) {
    int i = blockIdx.x * blockDim.x + threadIdx.x;
    if (i < E) {
        int pos = atomicAdd(&cursor[dst[i]], 1);
        adj[pos] = src[i];
    }
}

// ================= weight prep: W[K,N] -> bf16 image, SW128, 64-k chunks =======
__global__ void wbf16_kernel(const float* __restrict__ W, int K, int N,
                             __nv_bfloat16* __restrict__ hi) {
    int idx = blockIdx.x * blockDim.x + threadIdx.x;
    if (idx >= K * N) return;
    int k = idx / N, n = idx % N;
    __nv_bfloat16 h = __float2bfloat16(W[(size_t)k * N + n]);
    int c = k >> 6, kk = k & 63;
    uint32_t off = (uint32_t)(n * 128 + kk * 2);
    uint32_t sw = off ^ ((off >> 3) & 0x70);
    hi[((size_t)c * N * 128 + sw) / 2] = h;
}

// ================= GEMM1: persistent bf16 1-term, 512 threads =================
// C[M,128](bf16) = bf16(A[M,256] fp32) @ W1^T.  fp32->bf16 converted on load.
__global__ __launch_bounds__(512, 1)
void gemm1_bf16(const float* __restrict__ A, int lda,
                const __nv_bfloat16* __restrict__ imgHi,
                __nv_bfloat16* __restrict__ C, int M, int ntiles)
{
    constexpr int NT  = HIDF;        // 128
    constexpr int KCH = 4;           // 4 chunks of 64 k
    constexpr int BCH = NT * 128;    // 16KB weight chunk (bf16)
    constexpr int BB  = KCH * BCH;   // 64KB weights
    constexpr int OFF_A = BB;
    constexpr int ASTG = 16384;      // A stage: 128 rows x 128B (bf16)
    constexpr int NF  = 4;           // 32 cols per warp

    extern __shared__ char smraw[];
    char* sp = (char*)((((uintptr_t)smraw) + 1023) & ~(uintptr_t)1023);
    const uint32_t sb = smem_u32(sp);
    const uint32_t sbA = sb + OFF_A;

    const int tid = threadIdx.x;
    const int wid = tid >> 5;
    const int l   = tid & 31;
    const int warp_m = wid & 3;      // 32 rows each
    const int warp_n = wid >> 2;     // 32 cols each

    // W1 image -> SMEM once
    {
        const uint4* s = (const uint4*)imgHi;
        uint4* d = (uint4*)sp;
        for (int i = tid; i < BB / 16; i += 512) d[i] = s[i];
    }

    const uint32_t xorm = (uint32_t)(l & 7) << 4;
    const uint32_t aRow = warp_m * 32 + (l & 15);
    const uint32_t aK8  = (uint32_t)(l >> 4) * 8;
    const uint32_t bN   = warp_n * 32 + (l & 7);
    const uint32_t bK8  = (uint32_t)((l >> 3) & 1) * 8;
    const int g  = l >> 2;
    const int t2 = (l & 3) * 2;

    for (int tile = blockIdx.x; tile < ntiles; tile += gridDim.x) {
        const int blockRow = tile * 128;

        float acc[2][NF][4];
        #pragma unroll
        for (int i = 0; i < 2; i++)
            #pragma unroll
            for (int j = 0; j < NF; j++)
                #pragma unroll
                for (int q = 0; q < 4; q++) acc[i][j][q] = 0.f;

        // prefetch chunk 0 (fp32) into regs
        float4 pf[4];
        #pragma unroll
        for (int v = 0; v < 4; v++) {
            int vid = tid + v * 512;
            int grow = blockRow + (vid >> 4);
            pf[v] = make_float4(0.f, 0.f, 0.f, 0.f);
            if (grow < M) pf[v] = *(const float4*)(A + (size_t)grow * lda + (vid & 15) * 4);
        }

        for (int c = 0; c < KCH; c++) {
            const int buf = c & 1;
            char* aBase = sp + OFF_A + buf * ASTG;

            // convert prefetched fp32 -> bf16, store swizzled
            #pragma unroll
            for (int v = 0; v < 4; v++) {
                int vid = tid + v * 512;
                int row = vid >> 4;
                int kq  = vid & 15;
                float4 xv = pf[v];
                __nv_bfloat162 p01 = __floats2bfloat162_rn(xv.x, xv.y);
                __nv_bfloat162 p23 = __floats2bfloat162_rn(xv.z, xv.w);
                uint32_t off = (uint32_t)(row * 128 + kq * 8);
                uint32_t sw = off ^ ((off >> 3) & 0x70);
                *(uint2*)(aBase + sw) = make_uint2(*reinterpret_cast<uint32_t*>(&p01),
                                                   *reinterpret_cast<uint32_t*>(&p23));
            }
            __syncthreads();

            // prefetch next chunk (LDG overlaps MMA below)
            if (c + 1 < KCH) {
                #pragma unroll
                for (int v = 0; v < 4; v++) {
                    int vid = tid + v * 512;
                    int grow = blockRow + (vid >> 4);
                    pf[v] = make_float4(0.f, 0.f, 0.f, 0.f);
                    if (grow < M)
                        pf[v] = *(const float4*)(A + (size_t)grow * lda + (c + 1) * 64 + (vid & 15) * 4);
                }
            }

            const uint32_t aB = sbA + buf * ASTG + aRow * 128;
            const uint32_t bHiBase = sb + c * BCH + bN * 128;
            #pragma unroll
            for (int s = 0; s < 4; s++) {
                const uint32_t akOff = ((uint32_t)(s * 16 + aK8) * 2) ^ xorm;
                const uint32_t bkOff = ((uint32_t)(s * 16 + bK8) * 2) ^ xorm;
                uint32_t bh[NF][2];
                #pragma unroll
                for (int j = 0; j < NF; j++)
                    ldsm_x2(bh[j], bHiBase + j * 1024 + bkOff);
                #pragma unroll
                for (int i = 0; i < 2; i++) {
                    uint32_t ah[4];
                    ldsm_x4(ah, aB + i * 2048 + akOff);
                    #pragma unroll
                    for (int j = 0; j < NF; j++)
                        mma_bf16(acc[i][j], ah, bh[j]);
                }
            }
            __syncthreads();
        }

        #pragma unroll
        for (int i = 0; i < 2; i++) {
            int row0 = blockRow + warp_m * 32 + i * 16 + g;
            #pragma unroll
            for (int j = 0; j < NF; j++) {
                int col = warp_n * 32 + j * 8 + t2;
                if (row0 < M) {
                    __nv_bfloat162 v = __floats2bfloat162_rn(acc[i][j][0], acc[i][j][1]);
                    *(__nv_bfloat162*)(C + (size_t)row0 * NT + col) = v;
                }
                if (row0 + 8 < M) {
                    __nv_bfloat162 v = __floats2bfloat162_rn(acc[i][j][2], acc[i][j][3]);
                    *(__nv_bfloat162*)(C + (size_t)(row0 + 8) * NT + col) = v;
                }
            }
        }
    }
}

// ================= GEMM2: persistent bf16 1-term, cp.async, 4 CTA/SM ===========
__global__ __launch_bounds__(256, 4)
void bf16_gemm(const __nv_bfloat16* __restrict__ A, int lda,
               const __nv_bfloat16* __restrict__ imgHi,
               __nv_bfloat16* __restrict__ C, int M, int ntiles)
{
    constexpr int NT  = OUTF;
    constexpr int KCH = 2;
    constexpr int BCH = NT * 128;
    constexpr int BB  = KCH * BCH;
    constexpr int OFF_A = BB;
    constexpr int ASTG = 16384;
    constexpr int NTW = NT / 4;
    constexpr int NF  = NTW / 8;

    extern __shared__ char smraw[];
    char* sp = (char*)((((uintptr_t)smraw) + 1023) & ~(uintptr_t)1023);
    const uint32_t sb = smem_u32(sp);
    const uint32_t sbA = sb + OFF_A;

    const int tid = threadIdx.x;
    const int wid = tid >> 5;
    const int l   = tid & 31;
    const int warp_m = wid & 1;
    const int warp_n = wid >> 1;

    {
        const uint4* shi = (const uint4*)imgHi;
        uint4* dhi = (uint4*)sp;
        for (int i = tid; i < BB / 16; i += 256) dhi[i] = shi[i];
    }

    const uint32_t xorm = (uint32_t)(l & 7) << 4;
    const uint32_t aRow = warp_m * 64 + (l & 15);
    const uint32_t aK8  = (uint32_t)(l >> 4) * 8;
    const uint32_t bN   = warp_n * NTW + (l & 7);
    const uint32_t bK8  = (uint32_t)((l >> 3) & 1) * 8;
    const int g  = l >> 2;
    const int t2 = (l & 3) * 2;

    for (int tile = blockIdx.x; tile < ntiles; tile += gridDim.x) {
        const int blockRow = tile * 128;

        float acc[4][NF][4];
        #pragma unroll
        for (int i = 0; i < 4; i++)
            #pragma unroll
            for (int j = 0; j < NF; j++)
                #pragma unroll
                for (int q = 0; q < 4; q++) acc[i][j][q] = 0.f;

        #pragma unroll
        for (int v = 0; v < 4; v++) {
            int vid = tid + v * 256;
            int row = vid >> 3;
            int u   = vid & 7;
            int grow = blockRow + row;
            bool valid = grow < M;
            const __nv_bfloat16* src = A + (size_t)(valid ? grow : 0) * lda + u * 8;
            uint32_t dst = sbA + row * 128 + (((uint32_t)u * 16) ^ (((uint32_t)row & 7) << 4));
            cp16(dst, src, valid);
        }
        CP_COMMIT();

        for (int c = 0; c < KCH; c++) {
            const int buf = c & 1;
            if (c + 1 < KCH) {
                const int nb = (c + 1) & 1;
                #pragma unroll
                for (int v = 0; v < 4; v++) {
                    int vid = tid + v * 256;
                    int row = vid >> 3;
                    int u   = vid & 7;
                    int grow = blockRow + row;
                    bool valid = grow < M;
                    const __nv_bfloat16* src = A + (size_t)(valid ? grow : 0) * lda + (c + 1) * 64 + u * 8;
                    uint32_t dst = sbA + nb * ASTG + row * 128
                                 + (((uint32_t)u * 16) ^ (((uint32_t)row & 7) << 4));
                    cp16(dst, src, valid);
                }
                CP_COMMIT();
                CP_WAIT(1);
            } else {
                CP_WAIT(0);
            }
            __syncthreads();

            const uint32_t aB = sbA + buf * ASTG + aRow * 128;
            const uint32_t bHiBase = sb + c * BCH + bN * 128;
            #pragma unroll
            for (int s = 0; s < 4; s++) {
                const uint32_t akOff = ((uint32_t)(s * 16 + aK8) * 2) ^ xorm;
                const uint32_t bkOff = ((uint32_t)(s * 16 + bK8) * 2) ^ xorm;
                uint32_t bh[NF][2];
                #pragma unroll
                for (int j = 0; j < NF; j++)
                    ldsm_x2(bh[j], bHiBase + j * 1024 + bkOff);
                #pragma unroll
                for (int i = 0; i < 4; i++) {
                    uint32_t ah[4];
                    ldsm_x4(ah, aB + i * 2048 + akOff);
                    #pragma unroll
                    for (int j = 0; j < NF; j++)
                        mma_bf16(acc[i][j], ah, bh[j]);
                }
            }
            __syncthreads();
        }

        #pragma unroll
        for (int i = 0; i < 4; i++) {
            int row0 = blockRow + warp_m * 64 + i * 16 + g;
            #pragma unroll
            for (int j = 0; j < NF; j++) {
                int col = warp_n * NTW + j * 8 + t2;
                if (row0 < M) {
                    __nv_bfloat162 v = __floats2bfloat162_rn(acc[i][j][0], acc[i][j][1]);
                    *(__nv_bfloat162*)(C + (size_t)row0 * NT + col) = v;
                }
                if (row0 + 8 < M) {
                    __nv_bfloat162 v = __floats2bfloat162_rn(acc[i][j][2], acc[i][j][3]);
                    *(__nv_bfloat162*)(C + (size_t)(row0 + 8) * NT + col) = v;
                }
            }
        }
    }
}

// ================= agg1: 16 lanes/node, uint4 loads, 4-edge unroll =============
__global__ void agg1_kernel(const __nv_bfloat16* __restrict__ h, const int* __restrict__ rowptr,
                            const int* __restrict__ adj, const float* __restrict__ dinv,
                            const float* __restrict__ b1, __nv_bfloat16* __restrict__ h2, int n)
{
    int node = (blockIdx.x * blockDim.x + threadIdx.x) >> 4;
    int sub  = threadIdx.x & 15;
    if (node >= n) return;
    int beg = rowptr[node], end = rowptr[node + 1];
    float dd = dinv[node];
    const size_t fo = (size_t)sub * 8;

    float acc[8];
    #pragma unroll
    for (int i = 0; i < 8; i++) acc[i] = 0.f;

    int e = beg;
    for (; e + 4 <= end; e += 4) {
        int s0 = __ldg(adj + e),     s1 = __ldg(adj + e + 1);
        int s2 = __ldg(adj + e + 2), s3 = __ldg(adj + e + 3);
        float n0 = __ldg(dinv + s0) * dd, n1 = __ldg(dinv + s1) * dd;
        float n2 = __ldg(dinv + s2) * dd, n3 = __ldg(dinv + s3) * dd;
        uint4 q0 = *(const uint4*)(h + (size_t)s0 * HIDF + fo);
        uint4 q1 = *(const uint4*)(h + (size_t)s1 * HIDF + fo);
        uint4 q2 = *(const uint4*)(h + (size_t)s2 * HIDF + fo);
        uint4 q3 = *(const uint4*)(h + (size_t)s3 * HIDF + fo);
        acc8(acc, q0, n0); acc8(acc, q1, n1); acc8(acc, q2, n2); acc8(acc, q3, n3);
    }
    for (; e < end; e++) {
        int s0 = __ldg(adj + e);
        float n0 = __ldg(dinv + s0) * dd;
        uint4 q0 = *(const uint4*)(h + (size_t)s0 * HIDF + fo);
        acc8(acc, q0, n0);
    }

    float d2 = dd * dd;
    uint4 qs = *(const uint4*)(h + (size_t)node * HIDF + fo);
    float sf[8]; bq8(qs, sf);
    float4 bv0 = *(const float4*)(b1 + fo);
    float4 bv1 = *(const float4*)(b1 + fo + 4);
    float bb[8] = {bv0.x, bv0.y, bv0.z, bv0.w, bv1.x, bv1.y, bv1.z, bv1.w};
    uint32_t o[4];
    #pragma unroll
    for (int i = 0; i < 4; i++) {
        float t0 = fmaf(d2, sf[2*i],   acc[2*i])   + bb[2*i];
        float t1 = fmaf(d2, sf[2*i+1], acc[2*i+1]) + bb[2*i+1];
        float r0 = 0.9f * fmaxf(t0, 0.f) + 0.1f;
        float r1 = 0.9f * fmaxf(t1, 0.f) + 0.1f;
        __nv_bfloat162 p = __floats2bfloat162_rn(r0, r1);
        o[i] = *reinterpret_cast<uint32_t*>(&p);
    }
    *(uint4*)(h2 + (size_t)node * HIDF + fo) = make_uint4(o[0], o[1], o[2], o[3]);
}

// ================= agg2: 8 lanes/node, uint4 loads, 4-edge unroll ==============
__global__ void agg2_kernel(const __nv_bfloat16* __restrict__ g, const int* __restrict__ rowptr,
                            const int* __restrict__ adj, const float* __restrict__ dinv,
                            const float* __restrict__ b2, float* __restrict__ out, int n)
{
    int node = (blockIdx.x * blockDim.x + threadIdx.x) >> 3;
    int sub  = threadIdx.x & 7;
    if (node >= n) return;
    int beg = rowptr[node], end = rowptr[node + 1];
    float dd = dinv[node];
    const size_t fo = (size_t)sub * 8;

    float acc[8];
    #pragma unroll
    for (int i = 0; i < 8; i++) acc[i] = 0.f;

    int e = beg;
    for (; e + 4 <= end; e += 4) {
        int s0 = __ldg(adj + e),     s1 = __ldg(adj + e + 1);
        int s2 = __ldg(adj + e + 2), s3 = __ldg(adj + e + 3);
        float n0 = __ldg(dinv + s0) * dd, n1 = __ldg(dinv + s1) * dd;
        float n2 = __ldg(dinv + s2) * dd, n3 = __ldg(dinv + s3) * dd;
        uint4 q0 = *(const uint4*)(g + (size_t)s0 * OUTF + fo);
        uint4 q1 = *(const uint4*)(g + (size_t)s1 * OUTF + fo);
        uint4 q2 = *(const uint4*)(g + (size_t)s2 * OUTF + fo);
        uint4 q3 = *(const uint4*)(g + (size_t)s3 * OUTF + fo);
        acc8(acc, q0, n0); acc8(acc, q1, n1); acc8(acc, q2, n2); acc8(acc, q3, n3);
    }
    for (; e < end; e++) {
        int s0 = __ldg(adj + e);
        float n0 = __ldg(dinv + s0) * dd;
        uint4 q0 = *(const uint4*)(g + (size_t)s0 * OUTF + fo);
        acc8(acc, q0, n0);
    }

    float d2 = dd * dd;
    uint4 qs = *(const uint4*)(g + (size_t)node * OUTF + fo);
    float sf[8]; bq8(qs, sf);
    float4 bv0 = *(const float4*)(b2 + fo);
    float4 bv1 = *(const float4*)(b2 + fo + 4);
    float bb[8] = {bv0.x, bv0.y, bv0.z, bv0.w, bv1.x, bv1.y, bv1.z, bv1.w};
    float v[8];
    #pragma unroll
    for (int i = 0; i < 8; i++) v[i] = fmaf(d2, sf[i], acc[i]) + bb[i];

    float m = v[0];
    #pragma unroll
    for (int i = 1; i < 8; i++) m = fmaxf(m, v[i]);
    #pragma unroll
    for (int o = 4; o > 0; o >>= 1) m = fmaxf(m, __shfl_xor_sync(~0u, m, o, 8));
    float s = 0.f;
    #pragma unroll
    for (int i = 0; i < 8; i++) s += expf(v[i] - m);
    #pragma unroll
    for (int o = 4; o > 0; o >>= 1) s += __shfl_xor_sync(~0u, s, o, 8);
    float ls = m + logf(s);

    float* op = out + (size_t)node * OUTF + fo;
    *(float4*)(op)     = make_float4(v[0]-ls, v[1]-ls, v[2]-ls, v[3]-ls);
    *(float4*)(op + 4) = make_float4(v[4]-ls, v[5]-ls, v[6]-ls, v[7]-ls);
}

// ================= launch =======================================================
extern "C" void kernel_launch(void* const* d_in, const int* in_sizes, int n_in,
                              void* d_out, int out_size)
{
    const float* x  = (const float*)d_in[0];
    const int*   ei = (const int*)  d_in[1];
    // d_in[2] edge_weight: unused (CRF softmax over singleton groups == 1.0)
    const float* W1 = (const float*)d_in[3];
    const float* b1 = (const float*)d_in[4];
    const float* W2 = (const float*)d_in[5];
    const float* b2 = (const float*)d_in[6];
    float* out = (float*)d_out;

    const int n = in_sizes[0] / INF;
    const int E = in_sizes[2];
    const int* src = ei;
    const int* dst = ei + E;

    __nv_bfloat16 *h, *h2, *g, *w1hi, *w2hi;
    float *dinv;
    int *cnt, *rowptr, *cursor, *adj, *bsum, *boff;
    cudaGetSymbolAddress((void**)&h,     g_h);
    cudaGetSymbolAddress((void**)&h2,    g_h2);
    cudaGetSymbolAddress((void**)&g,     g_g);
    cudaGetSymbolAddress((void**)&dinv,  g_dinv);
    cudaGetSymbolAddress((void**)&cnt,   g_cnt);
    cudaGetSymbolAddress((void**)&rowptr,g_rowptr);
    cudaGetSymbolAddress((void**)&cursor,g_cursor);
    cudaGetSymbolAddress((void**)&adj,   g_adj);
    cudaGetSymbolAddress((void**)&bsum,  g_bsum);
    cudaGetSymbolAddress((void**)&boff,  g_boff);
    cudaGetSymbolAddress((void**)&w1hi,  g_w1hi);
    cudaGetSymbolAddress((void**)&w2hi,  g_w2hi);

    const int nb = (n + SCAN_BS - 1) / SCAN_BS;
    const int mtiles = (n + 127) / 128;

    constexpr int SMEM1 = INF * HIDF * 2 + 2 * 16384 + 1024;   // 64K wts + 32K A + pad
    constexpr int SMEM2 = HIDF * OUTF * 2 + 2 * 16384 + 1024;  // 16K wts + 32K A + pad
    cudaFuncSetAttribute(gemm1_bf16, cudaFuncAttributeMaxDynamicSharedMemorySize, SMEM1);
    cudaFuncSetAttribute(bf16_gemm,  cudaFuncAttributeMaxDynamicSharedMemorySize, SMEM2);

    static cudaStream_t sCsr = nullptr;
    static cudaEvent_t evFork = nullptr, evJoin = nullptr;
    if (!sCsr) {
        cudaStreamCreateWithFlags(&sCsr, cudaStreamNonBlocking);
        cudaEventCreateWithFlags(&evFork, cudaEventDisableTiming);
        cudaEventCreateWithFlags(&evJoin, cudaEventDisableTiming);
    }

    cudaEventRecord(evFork, 0);
    cudaStreamWaitEvent(sCsr, evFork, 0);

    // submission order puts gemm1_bf16 at launch slot 5 for ncu (-s 5):
    cudaMemsetAsync(cnt, 0, (size_t)n * sizeof(int), sCsr);                     // 1
    count_kernel<<<(E + 255)/256, 256, 0, sCsr>>>(dst, E, cnt);                 // 2
    scanA_kernel<<<nb, SCAN_BS, 0, sCsr>>>(cnt, n, bsum);                       // 3
    wbf16_kernel<<<(INF*HIDF + 255)/256, 256>>>(W1, INF, HIDF, w1hi);           // 4
    gemm1_bf16<<<148, 512, SMEM1>>>(x, INF, w1hi, h, n, mtiles);                // 5
    scanB_kernel<<<1, 128, 0, sCsr>>>(bsum, nb, boff, rowptr, n, E);            // 6
    scanC_kernel<<<nb, SCAN_BS, 0, sCsr>>>(cnt, boff, n, rowptr, cursor, dinv); // 7
    fill_kernel <<<(E + 255)/256, 256, 0, sCsr>>>(src, dst, E, cursor, adj);    // 8
    wbf16_kernel<<<(HIDF*OUTF + 255)/256, 256, 0, sCsr>>>(W2, HIDF, OUTF, w2hi);
    cudaEventRecord(evJoin, sCsr);
    cudaStreamWaitEvent(0, evJoin, 0);

    agg1_kernel<<<((long long)n*16 + 255)/256, 256>>>(h, rowptr, adj, dinv, b1, h2, n);
    bf16_gemm<<<592, 256, SMEM2>>>(h2, HIDF, w2hi, g, n, mtiles);
    agg2_kernel<<<((long long)n*8 + 255)/256, 256>>>(g, rowptr, adj, dinv, b2, out, n);
}